// round 6
// baseline (speedup 1.0000x reference)
#include <cuda_runtime.h>
#include <math.h>
#include <stdint.h>

#define BATCH 2
#define SEQ   4096
#define EMB   512
#define NH    8
#define HD    64
#define BHTOT (BATCH*NH)
#define NROWS (BATCH*SEQ)

__device__ float g_Q[BHTOT*SEQ*HD];   // [bh][s][hd], pre-scaled by 0.125*log2e, tf32-rounded
__device__ float g_K[BHTOT*SEQ*HD];   // [bh][s][hd], tf32-rounded
__device__ float g_V[BHTOT*SEQ*HD];   // [bh][s][hd], tf32-rounded
__device__ float g_ctx[NROWS*EMB];
__device__ float g_maskbias[NROWS];

// ---------------- helpers ----------------
__device__ __forceinline__ uint32_t smem_u32(const void* p){
    uint32_t a; asm("{ .reg .u64 t; cvta.to.shared.u64 t, %1; cvt.u32.u64 %0, t; }":"=r"(a):"l"(p)); return a;
}
__device__ __forceinline__ float ex2f(float x){ float y; asm("ex2.approx.f32 %0, %1;":"=f"(y):"f"(x)); return y; }
__device__ __forceinline__ uint32_t tf32r(float x){
    uint32_t u; asm("cvt.rna.tf32.f32 %0, %1;":"=r"(u):"f"(x)); return u;
}
__device__ __forceinline__ void cp16(uint32_t d, const void* s){
    asm volatile("cp.async.cg.shared.global [%0], [%1], 16;"::"r"(d),"l"(s)); }
__device__ __forceinline__ void cp4(uint32_t d, const void* s){
    asm volatile("cp.async.ca.shared.global [%0], [%1], 4;"::"r"(d),"l"(s)); }
#define CP_COMMIT() asm volatile("cp.async.commit_group;":::"memory")
#define CP_WAIT1()  asm volatile("cp.async.wait_group 1;":::"memory")
#define CP_WAIT0()  asm volatile("cp.async.wait_group 0;":::"memory")

#define MMA(c,a,b0,b1) asm volatile( \
    "mma.sync.aligned.m16n8k8.row.col.f32.tf32.tf32.f32 " \
    "{%0,%1,%2,%3},{%4,%5,%6,%7},{%8,%9},{%0,%1,%2,%3};" \
    : "+f"((c)[0]),"+f"((c)[1]),"+f"((c)[2]),"+f"((c)[3]) \
    : "r"((a)[0]),"r"((a)[1]),"r"((a)[2]),"r"((a)[3]),"r"(b0),"r"(b1))

// ---------------- mask expand ----------------
__global__ void mask_kernel(const unsigned char* __restrict__ mraw){
    __shared__ int flag;
    if (threadIdx.x==0) flag=0;
    __syncthreads();
    int any=0;
    for (int i=threadIdx.x;i<NROWS;i+=blockDim.x) any |= (mraw[i]!=0);
    if (any) atomicOr(&flag,1);
    __syncthreads();
    const int bytemode=flag; const int* mi=(const int*)mraw;
    for (int i=threadIdx.x;i<NROWS;i+=blockDim.x){
        bool m = bytemode ? (mraw[i]!=0) : (mi[i]!=0);
        g_maskbias[i] = m ? -1e30f : 0.0f;
    }
}

// ================= tf32 mma GEMM (unchanged from R5) =================
#define MG_STR  36
#define MG_TILEF 4608
#define MG_SMEM 73728

__device__ __forceinline__ void mg_load(uint32_t sb, const float* X, const float* W,
                                        int rowbase, int colbase, int kt, int tid){
    const int buf = kt&1;
#pragma unroll
    for (int p=0;p<4;p++){
        int idx = tid + p*256;
        int r = idx>>3, ch = idx&7;
        cp16(sb + buf*18432 + r*144 + ch*16, X + (size_t)(rowbase+r)*EMB + kt*32 + ch*4);
        cp16(sb + 36864 + buf*18432 + r*144 + ch*16, W + (size_t)(colbase+r)*EMB + kt*32 + ch*4);
    }
}

extern __shared__ char dynsm[];

__global__ __launch_bounds__(256)
void mma_gemm(const float* __restrict__ X, const float* __restrict__ W,
              const float* __restrict__ bias, float* __restrict__ out, int mode)
{
    const uint32_t sb = smem_u32(dynsm);
    float* smF = (float*)dynsm;
    const int tid=threadIdx.x, wid=tid>>5, lane=tid&31;
    const int g = lane>>2, q4 = lane&3;
    const int wm = wid&1, wn = wid>>1;
    const int rowbase = blockIdx.y*128, colbase = blockIdx.x*128;

    mg_load(sb, X, W, rowbase, colbase, 0, tid); CP_COMMIT();
    mg_load(sb, X, W, rowbase, colbase, 1, tid); CP_COMMIT();

    float acc[4][4][4];
#pragma unroll
    for (int mi=0;mi<4;mi++)
#pragma unroll
        for (int ji=0;ji<4;ji++)
#pragma unroll
            for (int x=0;x<4;x++) acc[mi][ji][x]=0.f;

    for (int kt=0;kt<16;kt++){
        const int buf = kt&1;
        CP_WAIT1();
        __syncthreads();
        const float* Xf = smF + buf*MG_TILEF;
        const float* Wf = smF + 9216 + buf*MG_TILEF;
#pragma unroll
        for (int c=0;c<4;c++){
            uint32_t a[4][4], bf[4][2];
#pragma unroll
            for (int mi=0;mi<4;mi++){
                const float* qp = Xf + (wm*64+mi*16+g)*MG_STR + c*8 + q4;
                a[mi][0]=tf32r(qp[0]); a[mi][1]=tf32r(qp[8*MG_STR]);
                a[mi][2]=tf32r(qp[4]); a[mi][3]=tf32r(qp[8*MG_STR+4]);
            }
#pragma unroll
            for (int ji=0;ji<4;ji++){
                const float* kp = Wf + (wn*32+ji*8+g)*MG_STR + c*8 + q4;
                bf[ji][0]=tf32r(kp[0]); bf[ji][1]=tf32r(kp[4]);
            }
#pragma unroll
            for (int mi=0;mi<4;mi++)
#pragma unroll
                for (int ji=0;ji<4;ji++)
                    MMA(acc[mi][ji], a[mi], bf[ji][0], bf[ji][1]);
        }
        __syncthreads();
        if (kt < 14) mg_load(sb, X, W, rowbase, colbase, kt+2, tid);
        CP_COMMIT();
    }

#pragma unroll
    for (int mi=0;mi<4;mi++){
        const int r0 = rowbase + wm*64 + mi*16 + g;
#pragma unroll
        for (int ji=0;ji<4;ji++){
            const int e = colbase + wn*32 + ji*8 + 2*q4;
            float2 bv = *(const float2*)(bias + e);
#pragma unroll
            for (int half=0; half<2; half++){
                const int r = r0 + half*8;
                float2 v;
                v.x = acc[mi][ji][2*half+0] + bv.x;
                v.y = acc[mi][ji][2*half+1] + bv.y;
                if (mode==1){
                    *(float2*)(out + (size_t)r*EMB + e) = v;
                } else {
                    if (mode==3){ v.x=__uint_as_float(tf32r(v.x)); v.y=__uint_as_float(tf32r(v.y)); }
                    int bb_=r>>12, s=r&(SEQ-1), hh=e>>6, d=e&(HD-1);
                    *(float2*)(out + (((size_t)(bb_*NH+hh))*SEQ+s)*HD + d) = v;
                }
            }
        }
    }
}

// ---------------- RoPE ----------------
__global__ void rope_kernel(){
    const int total=BHTOT*SEQ*(HD/2);
    int gid=blockIdx.x*blockDim.x+threadIdx.x;
    if (gid>=total) return;
    int i=gid&31, row=gid>>5, s=row&(SEQ-1);
    float inv=powf(10000.0f, -(float)i/32.0f);
    float sn, cs; sincosf((float)s*inv,&sn,&cs);
    size_t base=(size_t)row*HD;
    const float qs=0.125f*1.44269504f;
    float q0=g_Q[base+i], q1=g_Q[base+i+32];
    g_Q[base+i]    = __uint_as_float(tf32r(qs*(q0*cs-q1*sn)));
    g_Q[base+i+32] = __uint_as_float(tf32r(qs*(q1*cs+q0*sn)));
    float k0=g_K[base+i], k1=g_K[base+i+32];
    g_K[base+i]    = __uint_as_float(tf32r(k0*cs-k1*sn));
    g_K[base+i+32] = __uint_as_float(tf32r(k1*cs+k0*sn));
}

// ================= flash attention: QK(i) + PV(i-1) pipelined =================
#define SM_Q_F   256
#define SM_K_F   17664
#define SM_V_F   26368
#define SM_P_F   35584
#define KBUF_F   4352
#define VBUF_F   4608
#define PWARP_F  2176
#define FSMEM    211968

__device__ __forceinline__ void load_K(uint32_t sb, int bh, int b, int t, int tid){
    const int buf = t&1;
    const float* Kg = g_K + ((size_t)bh*SEQ + t*64)*HD;
#pragma unroll
    for (int p=0;p<4;p++){
        int idx = tid + p*256;
        int r = idx>>4, ch = idx&15;
        cp16(sb + 70656 + buf*17408 + r*272 + ch*16, Kg + r*64 + ch*4);
    }
    if (tid < 64) cp4(sb + buf*256 + tid*4, g_maskbias + b*SEQ + t*64 + tid);
}
__device__ __forceinline__ void load_V(uint32_t sb, int bh, int t, int tid){
    const int buf = t&1;
    const float* Vg = g_V + ((size_t)bh*SEQ + t*64)*HD;
#pragma unroll
    for (int p=0;p<4;p++){
        int idx = tid + p*256;
        int r = idx>>4, ch = idx&15;
        cp16(sb + 105472 + buf*18432 + r*288 + ch*16, Vg + r*64 + ch*4);
    }
}

__global__ __launch_bounds__(256,1) void flash_mma()
{
    float* smF = (float*)dynsm;
    uint32_t* smU = (uint32_t*)dynsm;
    const uint32_t sb = smem_u32(dynsm);
    const int tid=threadIdx.x, wid=tid>>5, lane=tid&31;
    const int g = lane>>2, q4 = lane&3;
    const int bh=blockIdx.y, b=bh>>3, h=bh&7;
    const int q0=blockIdx.x*256;

    // prologue: group0 = {Q tile, K0, mb0}; group1 = {K1, V0, mb1}
    {
        const float* Qg = g_Q + ((size_t)bh*SEQ + q0)*HD;
#pragma unroll
        for (int p=0;p<16;p++){
            int idx = tid + p*256;
            int row = idx>>4, ch = idx&15;
            cp16(sb + 1024 + row*272 + ch*16, Qg + row*64 + ch*4);
        }
    }
    load_K(sb, bh, b, 0, tid);
    CP_COMMIT();
    load_K(sb, bh, b, 1, tid);
    load_V(sb, bh, 0, tid);
    CP_COMMIT();

    float o[2][8][4];
#pragma unroll
    for (int m=0;m<2;m++)
#pragma unroll
        for (int j=0;j<8;j++)
#pragma unroll
            for (int x=0;x<4;x++) o[m][j][x]=0.f;
    float rsum[4] = {0.f,0.f,0.f,0.f};

    uint32_t* Pw = smU + SM_P_F + wid*PWARP_F;
    const uint32_t* Qu = smU + SM_Q_F;

    for (int i=0;i<64;i++){
        const int buf = i&1;
        CP_WAIT1();
        __syncthreads();

        // ---- S = Q K(i)^T ----
        float s[2][8][4];
#pragma unroll
        for (int m=0;m<2;m++)
#pragma unroll
            for (int j=0;j<8;j++)
#pragma unroll
                for (int x=0;x<4;x++) s[m][j][x]=0.f;

        const uint32_t* Ku = smU + SM_K_F + buf*KBUF_F;
#pragma unroll
        for (int c=0;c<8;c++){
            uint32_t a[2][4];
#pragma unroll
            for (int m=0;m<2;m++){
                const uint32_t* qp = Qu + (wid*32 + m*16 + g)*68 + c*8 + q4;
                a[m][0]=qp[0]; a[m][1]=qp[8*68]; a[m][2]=qp[4]; a[m][3]=qp[8*68+4];
            }
#pragma unroll
            for (int j=0;j<8;j++){
                const uint32_t* kp = Ku + (j*8+g)*68 + c*8 + q4;
                uint32_t b0 = kp[0], b1 = kp[4];
                MMA(s[0][j], a[0], b0, b1);
                MMA(s[1][j], a[1], b0, b1);
            }
        }

        // ---- O += P(i-1) V(i-1) : keeps tensor pipe busy through softmax ----
        if (i > 0){
            const uint32_t* Vu = smU + SM_V_F + ((i-1)&1)*VBUF_F;
#pragma unroll
            for (int c=0;c<8;c++){
                uint32_t a[2][4];
#pragma unroll
                for (int m=0;m<2;m++){
                    const uint32_t* pp = Pw + (m*16+g)*68 + c*8 + q4;
                    a[m][0]=pp[0]; a[m][1]=pp[8*68]; a[m][2]=pp[4]; a[m][3]=pp[8*68+4];
                }
#pragma unroll
                for (int j=0;j<8;j++){
                    const uint32_t* vp = Vu + (c*8+q4)*72 + j*8 + g;
                    uint32_t b0 = vp[0], b1 = vp[4*72];
                    MMA(o[0][j], a[0], b0, b1);
                    MMA(o[1][j], a[1], b0, b1);
                }
            }
        }
        __syncwarp();   // PV(i-1) cross-lane P reads complete before rewriting Pw

        // ---- softmax(i): p = 2^(s + mb), write P(i) ----
        const float* mbF = smF + buf*64;
#pragma unroll
        for (int j=0;j<8;j++){
            float2 mb2 = *(const float2*)(mbF + j*8 + 2*q4);
#pragma unroll
            for (int m=0;m<2;m++){
                float p0 = ex2f(s[m][j][0] + mb2.x);
                float p1 = ex2f(s[m][j][1] + mb2.y);
                float p2 = ex2f(s[m][j][2] + mb2.x);
                float p3 = ex2f(s[m][j][3] + mb2.y);
                rsum[2*m]   += p0+p1;
                rsum[2*m+1] += p2+p3;
                uint2 u01; u01.x=tf32r(p0); u01.y=tf32r(p1);
                uint2 u23; u23.x=tf32r(p2); u23.y=tf32r(p3);
                *(uint2*)(Pw + (m*16+g  )*68 + j*8 + 2*q4) = u01;
                *(uint2*)(Pw + (m*16+g+8)*68 + j*8 + 2*q4) = u23;
            }
        }
        __syncthreads();   // all smem reads done before prefetch overwrites

        // prefetch: group(i+2) = {K(i+2), mb(i+2), V(i+1)}
        if (i < 62) load_K(sb, bh, b, i+2, tid);
        if (i < 63) load_V(sb, bh, i+1, tid);
        CP_COMMIT();
    }

    // ---- peeled final PV(63) ----
    CP_WAIT0();
    __syncthreads();
    {
        const uint32_t* Vu = smU + SM_V_F + 1*VBUF_F;   // V(63), buf 63&1=1
#pragma unroll
        for (int c=0;c<8;c++){
            uint32_t a[2][4];
#pragma unroll
            for (int m=0;m<2;m++){
                const uint32_t* pp = Pw + (m*16+g)*68 + c*8 + q4;
                a[m][0]=pp[0]; a[m][1]=pp[8*68]; a[m][2]=pp[4]; a[m][3]=pp[8*68+4];
            }
#pragma unroll
            for (int j=0;j<8;j++){
                const uint32_t* vp = Vu + (c*8+q4)*72 + j*8 + g;
                uint32_t b0 = vp[0], b1 = vp[4*72];
                MMA(o[0][j], a[0], b0, b1);
                MMA(o[1][j], a[1], b0, b1);
            }
        }
    }

    // ---- epilogue ----
    float inv[4];
#pragma unroll
    for (int x=0;x<4;x++){
        float r = rsum[x];
        r += __shfl_xor_sync(0xFFFFFFFF, r, 1);
        r += __shfl_xor_sync(0xFFFFFFFF, r, 2);
        inv[x] = 1.0f/r;
    }
#pragma unroll
    for (int m=0;m<2;m++){
        const int row0 = q0 + wid*32 + m*16 + g;
        float* d0 = g_ctx + ((size_t)(b*SEQ + row0  ))*EMB + h*HD;
        float* d1 = g_ctx + ((size_t)(b*SEQ + row0+8))*EMB + h*HD;
#pragma unroll
        for (int j=0;j<8;j++){
            float2 v0; v0.x = o[m][j][0]*inv[2*m];   v0.y = o[m][j][1]*inv[2*m];
            float2 v1; v1.x = o[m][j][2]*inv[2*m+1]; v1.y = o[m][j][3]*inv[2*m+1];
            *(float2*)(d0 + j*8 + 2*q4) = v0;
            *(float2*)(d1 + j*8 + 2*q4) = v1;
        }
    }
}

// ---------------- launch ----------------
extern "C" void kernel_launch(void* const* d_in, const int* in_sizes, int n_in,
                              void* d_out, int out_size)
{
    const float* query=(const float*)d_in[0];
    const float* key_ =(const float*)d_in[1];
    const float* value=(const float*)d_in[2];
    const float* Wq=(const float*)d_in[3];  const float* bq=(const float*)d_in[4];
    const float* Wk=(const float*)d_in[5];  const float* bk=(const float*)d_in[6];
    const float* Wv=(const float*)d_in[7];  const float* bv=(const float*)d_in[8];
    const float* Wo=(const float*)d_in[9];  const float* bo=(const float*)d_in[10];
    const unsigned char* mask=(const unsigned char*)d_in[11];

    float *Qd,*Kd,*Vd,*Cd;
    cudaGetSymbolAddress((void**)&Qd, g_Q);
    cudaGetSymbolAddress((void**)&Kd, g_K);
    cudaGetSymbolAddress((void**)&Vd, g_V);
    cudaGetSymbolAddress((void**)&Cd, g_ctx);

    cudaFuncSetAttribute(flash_mma, cudaFuncAttributeMaxDynamicSharedMemorySize, FSMEM);
    cudaFuncSetAttribute(mma_gemm, cudaFuncAttributeMaxDynamicSharedMemorySize, MG_SMEM);

    mask_kernel<<<1,256>>>(mask);

    dim3 mgrid(EMB/128, NROWS/128);
    mma_gemm<<<mgrid,256,MG_SMEM>>>(query, Wq, bq, Qd, 0);
    mma_gemm<<<mgrid,256,MG_SMEM>>>(key_,  Wk, bk, Kd, 0);
    mma_gemm<<<mgrid,256,MG_SMEM>>>(value, Wv, bv, Vd, 3);

    const int rope_total=BHTOT*SEQ*(HD/2);
    rope_kernel<<<(rope_total+255)/256,256>>>();

    flash_mma<<<dim3(SEQ/256, BHTOT), 256, FSMEM>>>();

    mma_gemm<<<mgrid,256,MG_SMEM>>>(Cd, Wo, bo, (float*)d_out, 1);
}

// round 7
// speedup vs baseline: 1.7370x; 1.7370x over previous
#include <cuda_runtime.h>
#include <cuda_fp16.h>
#include <math.h>
#include <stdint.h>

#define BATCH 2
#define SEQ   4096
#define EMB   512
#define NH    8
#define HD    64
#define BHTOT (BATCH*NH)
#define NROWS (BATCH*SEQ)
#define NE    (NROWS*EMB)
#define WE    (EMB*EMB)

// ---------------- fp16 scratch (static device globals) ----------------
__device__ __half g_Xh[3*NE];            // converted query/key/value inputs
__device__ __half g_Wh[4*WE];            // converted Wq/Wk/Wv/Wo
__device__ __half g_Qh[BHTOT*SEQ*HD];    // [bh][s][hd], rope'd, scaled by 0.125*log2e
__device__ __half g_Kh[BHTOT*SEQ*HD];    // [bh][s][hd], rope'd
__device__ __half g_Vt[BHTOT*HD*SEQ];    // transposed [bh][hd][s]
__device__ __half g_ctxh[NROWS*EMB];     // attention output, fp16
__device__ float  g_maskbias[NROWS];     // 0 or -1e30

// ---------------- helpers ----------------
__device__ __forceinline__ uint32_t smem_u32(const void* p){
    uint32_t a; asm("{ .reg .u64 t; cvta.to.shared.u64 t, %1; cvt.u32.u64 %0, t; }":"=r"(a):"l"(p)); return a;
}
__device__ __forceinline__ float ex2f(float x){ float y; asm("ex2.approx.f32 %0, %1;":"=f"(y):"f"(x)); return y; }
__device__ __forceinline__ uint32_t h2pack(float lo, float hi){
    uint32_t d; asm("cvt.rn.f16x2.f32 %0, %1, %2;":"=r"(d):"f"(hi),"f"(lo)); return d;
}
__device__ __forceinline__ void cp16(uint32_t d, const void* s){
    asm volatile("cp.async.cg.shared.global [%0], [%1], 16;"::"r"(d),"l"(s)); }
__device__ __forceinline__ void cp4(uint32_t d, const void* s){
    asm volatile("cp.async.ca.shared.global [%0], [%1], 4;"::"r"(d),"l"(s)); }
#define CP_COMMIT() asm volatile("cp.async.commit_group;":::"memory")
#define CP_WAIT1()  asm volatile("cp.async.wait_group 1;":::"memory")

// fp16 MMA, fp32 accumulate: m16n8k16
#define HMMA(c,a,b0,b1) asm volatile( \
    "mma.sync.aligned.m16n8k16.row.col.f32.f16.f16.f32 " \
    "{%0,%1,%2,%3},{%4,%5,%6,%7},{%8,%9},{%0,%1,%2,%3};" \
    : "+f"((c)[0]),"+f"((c)[1]),"+f"((c)[2]),"+f"((c)[3]) \
    : "r"((a)[0]),"r"((a)[1]),"r"((a)[2]),"r"((a)[3]),"r"(b0),"r"(b1))

extern __shared__ char dynsm[];

// ---------------- mask expand ----------------
__global__ void mask_kernel(const unsigned char* __restrict__ mraw){
    __shared__ int flag;
    if (threadIdx.x==0) flag=0;
    __syncthreads();
    int any=0;
    for (int i=threadIdx.x;i<NROWS;i+=blockDim.x) any |= (mraw[i]!=0);
    if (any) atomicOr(&flag,1);
    __syncthreads();
    const int bytemode=flag; const int* mi=(const int*)mraw;
    for (int i=threadIdx.x;i<NROWS;i+=blockDim.x){
        bool m = bytemode ? (mraw[i]!=0) : (mi[i]!=0);
        g_maskbias[i] = m ? -1e30f : 0.0f;
    }
}

// ---------------- fp32 -> fp16 converts ----------------
__global__ void convert_inputs(const float* __restrict__ q, const float* __restrict__ k,
                               const float* __restrict__ v){
    int idx = blockIdx.x*blockDim.x + threadIdx.x;
    if (idx >= 3*(NE/4)) return;
    int seg = idx / (NE/4), off = idx % (NE/4);
    const float* src = seg==0? q : (seg==1? k : v);
    float4 x = ((const float4*)src)[off];
    __half2* d = (__half2*)(g_Xh + (size_t)seg*NE + (size_t)off*4);
    d[0] = __floats2half2_rn(x.x, x.y);
    d[1] = __floats2half2_rn(x.z, x.w);
}
__global__ void convert_weights(const float* __restrict__ wq, const float* __restrict__ wk,
                                const float* __restrict__ wv, const float* __restrict__ wo){
    int idx = blockIdx.x*blockDim.x + threadIdx.x;
    if (idx >= 4*(WE/4)) return;
    int seg = idx / (WE/4), off = idx % (WE/4);
    const float* src = seg==0?wq:(seg==1?wk:(seg==2?wv:wo));
    float4 x = ((const float4*)src)[off];
    __half2* d = (__half2*)(g_Wh + (size_t)seg*WE + (size_t)off*4);
    d[0] = __floats2half2_rn(x.x, x.y);
    d[1] = __floats2half2_rn(x.z, x.w);
}

// ================= fp16 GEMM: C[n,e] = X[n,:]·W[e,:] + bias[e] =================
// CTA 128x128, 8 warps of 64x32, BK=32 double-buffered.
// mode 0: write fp16 [B,H,S,HD]; 1: write fp32 row-major; 2: write fp16 [B,H,HD,S] (V^T)
// SMEM: Xs 2 x (128 rows x 40 halves) @0; Ws same @20480. total 40960B.
__device__ __forceinline__ void hg_load(uint32_t sb, const __half* X, const __half* W,
                                        int rowbase, int colbase, int kt, int tid){
    const int buf = kt&1;
#pragma unroll
    for (int p=0;p<2;p++){
        int idx = tid + p*256;          // 0..511
        int r = idx>>2, ch = idx&3;
        cp16(sb + buf*10240 + r*80 + ch*16, X + (size_t)(rowbase+r)*EMB + kt*32 + ch*8);
        cp16(sb + 20480 + buf*10240 + r*80 + ch*16, W + (size_t)(colbase+r)*EMB + kt*32 + ch*8);
    }
}

__global__ __launch_bounds__(256,2)
void hgemm(const __half* __restrict__ X, const __half* __restrict__ W,
           const float* __restrict__ bias, void* __restrict__ out, int mode)
{
    const uint32_t sb = smem_u32(dynsm);
    const uint32_t* smU = (const uint32_t*)dynsm;
    const int tid=threadIdx.x, wid=tid>>5, lane=tid&31;
    const int g = lane>>2, q4 = lane&3;
    const int wm = wid&1, wn = wid>>1;
    const int rowbase = blockIdx.y*128, colbase = blockIdx.x*128;

    hg_load(sb, X, W, rowbase, colbase, 0, tid); CP_COMMIT();
    hg_load(sb, X, W, rowbase, colbase, 1, tid); CP_COMMIT();

    float acc[4][4][4];
#pragma unroll
    for (int mi=0;mi<4;mi++)
#pragma unroll
        for (int ji=0;ji<4;ji++)
#pragma unroll
            for (int x=0;x<4;x++) acc[mi][ji][x]=0.f;

    for (int kt=0;kt<16;kt++){
        const int buf = kt&1;
        CP_WAIT1();
        __syncthreads();
        const uint32_t* Xu = smU + buf*2560;          // 10240B/4
        const uint32_t* Wu = smU + 5120 + buf*2560;
#pragma unroll
        for (int c=0;c<2;c++){                        // two k=16 steps
            uint32_t a[4][4], bf[4][2];
#pragma unroll
            for (int mi=0;mi<4;mi++){
                const uint32_t* xp = Xu + (wm*64+mi*16+g)*20 + c*8 + q4;
                a[mi][0]=xp[0]; a[mi][1]=xp[8*20]; a[mi][2]=xp[4]; a[mi][3]=xp[8*20+4];
            }
#pragma unroll
            for (int ji=0;ji<4;ji++){
                const uint32_t* wp = Wu + (wn*32+ji*8+g)*20 + c*8 + q4;
                bf[ji][0]=wp[0]; bf[ji][1]=wp[4];
            }
#pragma unroll
            for (int mi=0;mi<4;mi++)
#pragma unroll
                for (int ji=0;ji<4;ji++)
                    HMMA(acc[mi][ji], a[mi], bf[ji][0], bf[ji][1]);
        }
        __syncthreads();
        if (kt < 14) hg_load(sb, X, W, rowbase, colbase, kt+2, tid);
        CP_COMMIT();
    }

    // epilogue
#pragma unroll
    for (int mi=0;mi<4;mi++){
        const int r0 = rowbase + wm*64 + mi*16 + g;
#pragma unroll
        for (int ji=0;ji<4;ji++){
            const int e = colbase + wn*32 + ji*8 + 2*q4;
            float2 bv = *(const float2*)(bias + e);
#pragma unroll
            for (int half=0; half<2; half++){
                const int r = r0 + half*8;
                float vx = acc[mi][ji][2*half+0] + bv.x;
                float vy = acc[mi][ji][2*half+1] + bv.y;
                if (mode==1){
                    float2 v; v.x=vx; v.y=vy;
                    *(float2*)((float*)out + (size_t)r*EMB + e) = v;
                } else {
                    int bb_=r>>12, s=r&(SEQ-1), hh=e>>6, d=e&(HD-1);
                    if (mode==0){
                        *(__half2*)((__half*)out + (((size_t)(bb_*NH+hh))*SEQ+s)*HD + d)
                            = __floats2half2_rn(vx, vy);
                    } else {  // mode 2: transposed V
                        __half* o = (__half*)out + ((size_t)(bb_*NH+hh))*HD*SEQ;
                        o[(size_t)d*SEQ + s]     = __float2half_rn(vx);
                        o[(size_t)(d+1)*SEQ + s] = __float2half_rn(vy);
                    }
                }
            }
        }
    }
}

// ---------------- RoPE on fp16 Q/K; Q scaled by 0.125*log2e ----------------
__global__ void rope_h(){
    const int total=BHTOT*SEQ*(HD/2);
    int gid=blockIdx.x*blockDim.x+threadIdx.x;
    if (gid>=total) return;
    int i=gid&31, row=gid>>5, s=row&(SEQ-1);
    float inv=powf(10000.0f, -(float)i/32.0f);
    float sn, cs; sincosf((float)s*inv,&sn,&cs);
    size_t base=(size_t)row*HD;
    const float qs=0.125f*1.44269504f;
    float q0=__half2float(g_Qh[base+i]), q1=__half2float(g_Qh[base+i+32]);
    g_Qh[base+i]    = __float2half_rn(qs*(q0*cs-q1*sn));
    g_Qh[base+i+32] = __float2half_rn(qs*(q1*cs+q0*sn));
    float k0=__half2float(g_Kh[base+i]), k1=__half2float(g_Kh[base+i+32]);
    g_Kh[base+i]    = __float2half_rn(k0*cs-k1*sn);
    g_Kh[base+i+32] = __float2half_rn(k1*cs+k0*sn);
}

// ================= fp16 flash attention =================
// CTA: 256 thr, 8 warps x 16 q-rows = 128 rows; BN=64 keys/iter; 64 iters.
// P stays in registers (QK C-frag == PV A-frag layout).
// SMEM bytes: MB@0 (2x64 f32, pad 1024), Q@1024 (128x144), K@19456 (2x9216),
//             V@37888 (2x9216).  FSMEM = 56320 -> 2 CTAs/SM.
#define FQ_B   1024
#define FK_B   19456
#define FV_B   37888
#define FSMEM  56320
#define FK_U   4864     /* 19456/4 */
#define FV_U   9472
#define FBUF_U 2304     /* 9216/4 */

__device__ __forceinline__ void f_loadK(uint32_t sb, int bh, int t, int tid){
#pragma unroll
    for (int p=0;p<2;p++){
        int idx = tid + p*256;          // 0..511
        int r = idx>>3, ch = idx&7;
        cp16(sb + FK_B + (t&1)*9216 + r*144 + ch*16,
             g_Kh + ((size_t)bh*SEQ + t*64 + r)*HD + ch*8);
    }
}
__device__ __forceinline__ void f_loadV(uint32_t sb, int bh, int t, int tid){
#pragma unroll
    for (int p=0;p<2;p++){
        int idx = tid + p*256;
        int r = idx>>3, ch = idx&7;     // r = hd row
        cp16(sb + FV_B + (t&1)*9216 + r*144 + ch*16,
             g_Vt + ((size_t)bh*HD + r)*SEQ + t*64 + ch*8);
    }
}
__device__ __forceinline__ void f_loadMB(uint32_t sb, int b, int t, int tid){
    if (tid < 64) cp4(sb + (t&1)*256 + tid*4, g_maskbias + b*SEQ + t*64 + tid);
}

__global__ __launch_bounds__(256,2) void flash_h()
{
    const float* smF = (const float*)dynsm;
    const uint32_t* smU = (const uint32_t*)dynsm;
    const uint32_t sb = smem_u32(dynsm);
    const int tid=threadIdx.x, wid=tid>>5, lane=tid&31;
    const int g = lane>>2, q4 = lane&3;
    const int bh=blockIdx.y, b=bh>>3, h=bh&7;
    const int q0=blockIdx.x*128;

    // prologue: group0 = {Q, K0, V0, mb0}; group1 = {K1, V1, mb1}
#pragma unroll
    for (int p=0;p<4;p++){
        int idx = tid + p*256;          // 0..1023
        int r = idx>>3, ch = idx&7;
        cp16(sb + FQ_B + r*144 + ch*16, g_Qh + ((size_t)bh*SEQ + q0 + r)*HD + ch*8);
    }
    f_loadK(sb, bh, 0, tid); f_loadV(sb, bh, 0, tid); f_loadMB(sb, b, 0, tid);
    CP_COMMIT();
    f_loadK(sb, bh, 1, tid); f_loadV(sb, bh, 1, tid); f_loadMB(sb, b, 1, tid);
    CP_COMMIT();

    float o[8][4];
#pragma unroll
    for (int j=0;j<8;j++)
#pragma unroll
        for (int x=0;x<4;x++) o[j][x]=0.f;
    float rs0=0.f, rs1=0.f;
    uint32_t qf[4][4];

    for (int i=0;i<64;i++){
        const int buf = i&1;
        CP_WAIT1();
        __syncthreads();

        if (i==0){   // Q fragments, cached for all iterations
            const uint32_t* Qu = smU + FQ_B/4;
#pragma unroll
            for (int c=0;c<4;c++){
                const uint32_t* qp = Qu + (wid*16+g)*36 + c*8 + q4;
                qf[c][0]=qp[0]; qf[c][1]=qp[8*36]; qf[c][2]=qp[4]; qf[c][3]=qp[8*36+4];
            }
        }

        // ---- S = Q K^T ----
        float s[8][4];
#pragma unroll
        for (int j=0;j<8;j++)
#pragma unroll
            for (int x=0;x<4;x++) s[j][x]=0.f;
        const uint32_t* Ku = smU + FK_U + buf*FBUF_U;
#pragma unroll
        for (int c=0;c<4;c++)
#pragma unroll
            for (int j=0;j<8;j++){
                const uint32_t* kp = Ku + (j*8+g)*36 + c*8 + q4;
                HMMA(s[j], qf[c], kp[0], kp[4]);
            }

        // ---- softmax: p = 2^(s+mb); pack to fp16 A-fragments in registers ----
        const float* mbF = smF + buf*64;
        uint32_t pp[8][2];
#pragma unroll
        for (int j=0;j<8;j++){
            float2 mb2 = *(const float2*)(mbF + j*8 + 2*q4);
            float p0 = ex2f(s[j][0] + mb2.x);
            float p1 = ex2f(s[j][1] + mb2.y);
            float p2 = ex2f(s[j][2] + mb2.x);
            float p3 = ex2f(s[j][3] + mb2.y);
            rs0 += p0+p1; rs1 += p2+p3;
            pp[j][0] = h2pack(p0, p1);
            pp[j][1] = h2pack(p2, p3);
        }

        // ---- O += P V (P in registers) ----
        const uint32_t* Vu = smU + FV_U + buf*FBUF_U;
#pragma unroll
        for (int c=0;c<4;c++){
            uint32_t A[4] = {pp[2*c][0], pp[2*c][1], pp[2*c+1][0], pp[2*c+1][1]};
#pragma unroll
            for (int jn=0;jn<8;jn++){
                const uint32_t* vp = Vu + (jn*8+g)*36 + c*8 + q4;
                HMMA(o[jn], A, vp[0], vp[4]);
            }
        }
        __syncthreads();

        if (i < 62){ f_loadK(sb, bh, i+2, tid); f_loadV(sb, bh, i+2, tid); f_loadMB(sb, b, i+2, tid); }
        CP_COMMIT();
    }

    // ---- epilogue ----
    rs0 += __shfl_xor_sync(0xFFFFFFFF, rs0, 1);
    rs0 += __shfl_xor_sync(0xFFFFFFFF, rs0, 2);
    rs1 += __shfl_xor_sync(0xFFFFFFFF, rs1, 1);
    rs1 += __shfl_xor_sync(0xFFFFFFFF, rs1, 2);
    const float inv0 = 1.0f/rs0, inv1 = 1.0f/rs1;
    const int row0 = q0 + wid*16 + g;
    __half* d0 = g_ctxh + ((size_t)(b*SEQ + row0  ))*EMB + h*HD;
    __half* d1 = g_ctxh + ((size_t)(b*SEQ + row0+8))*EMB + h*HD;
#pragma unroll
    for (int jn=0;jn<8;jn++){
        *(__half2*)(d0 + jn*8 + 2*q4) = __floats2half2_rn(o[jn][0]*inv0, o[jn][1]*inv0);
        *(__half2*)(d1 + jn*8 + 2*q4) = __floats2half2_rn(o[jn][2]*inv1, o[jn][3]*inv1);
    }
}

// ---------------- launch ----------------
extern "C" void kernel_launch(void* const* d_in, const int* in_sizes, int n_in,
                              void* d_out, int out_size)
{
    const float* query=(const float*)d_in[0];
    const float* key_ =(const float*)d_in[1];
    const float* value=(const float*)d_in[2];
    const float* Wq=(const float*)d_in[3];  const float* bq=(const float*)d_in[4];
    const float* Wk=(const float*)d_in[5];  const float* bk=(const float*)d_in[6];
    const float* Wv=(const float*)d_in[7];  const float* bv=(const float*)d_in[8];
    const float* Wo=(const float*)d_in[9];  const float* bo=(const float*)d_in[10];
    const unsigned char* mask=(const unsigned char*)d_in[11];

    __half *Xh,*Wh,*Qh,*Kh,*Vt,*Ch;
    cudaGetSymbolAddress((void**)&Xh, g_Xh);
    cudaGetSymbolAddress((void**)&Wh, g_Wh);
    cudaGetSymbolAddress((void**)&Qh, g_Qh);
    cudaGetSymbolAddress((void**)&Kh, g_Kh);
    cudaGetSymbolAddress((void**)&Vt, g_Vt);
    cudaGetSymbolAddress((void**)&Ch, g_ctxh);

    cudaFuncSetAttribute(flash_h, cudaFuncAttributeMaxDynamicSharedMemorySize, FSMEM);
    cudaFuncSetAttribute(hgemm,   cudaFuncAttributeMaxDynamicSharedMemorySize, 40960);

    mask_kernel<<<1,256>>>(mask);
    convert_inputs <<<(3*(NE/4)+255)/256,256>>>(query, key_, value);
    convert_weights<<<(4*(WE/4)+255)/256,256>>>(Wq, Wk, Wv, Wo);

    dim3 ggrid(EMB/128, NROWS/128);   // (4, 64)
    hgemm<<<ggrid,256,40960>>>(Xh,        Wh,        bq, Qh, 0);
    hgemm<<<ggrid,256,40960>>>(Xh + NE,   Wh + WE,   bk, Kh, 0);
    hgemm<<<ggrid,256,40960>>>(Xh + 2*NE, Wh + 2*WE, bv, Vt, 2);

    const int rope_total=BHTOT*SEQ*(HD/2);
    rope_h<<<(rope_total+255)/256,256>>>();

    flash_h<<<dim3(SEQ/128, BHTOT), 256, FSMEM>>>();

    hgemm<<<ggrid,256,40960>>>(Ch, Wh + 3*WE, bo, d_out, 1);
}

// round 8
// speedup vs baseline: 1.7760x; 1.0225x over previous
#include <cuda_runtime.h>
#include <cuda_fp16.h>
#include <math.h>
#include <stdint.h>

#define BATCH 2
#define SEQ   4096
#define EMB   512
#define NH    8
#define HD    64
#define BHTOT (BATCH*NH)
#define NROWS (BATCH*SEQ)
#define NE    (NROWS*EMB)
#define WE    (EMB*EMB)

// ---------------- fp16 scratch ----------------
__device__ __half g_Xh[3*NE];
__device__ __half g_Wh[4*WE];
__device__ __half g_Qh[BHTOT*SEQ*HD];    // rope'd, scaled by 0.125*log2e
__device__ __half g_Kh[BHTOT*SEQ*HD];
__device__ __half g_Vt[BHTOT*HD*SEQ];    // transposed [bh][hd][s]
__device__ __half g_ctxh[NROWS*EMB];
__device__ float  g_maskbias[NROWS];

// ---------------- helpers ----------------
__device__ __forceinline__ uint32_t smem_u32(const void* p){
    uint32_t a; asm("{ .reg .u64 t; cvta.to.shared.u64 t, %1; cvt.u32.u64 %0, t; }":"=r"(a):"l"(p)); return a;
}
__device__ __forceinline__ float ex2f(float x){ float y; asm("ex2.approx.f32 %0, %1;":"=f"(y):"f"(x)); return y; }
__device__ __forceinline__ uint32_t h2pack(float lo, float hi){
    uint32_t d; asm("cvt.rn.f16x2.f32 %0, %1, %2;":"=r"(d):"f"(hi),"f"(lo)); return d;
}
__device__ __forceinline__ void cp16(uint32_t d, const void* s){
    asm volatile("cp.async.cg.shared.global [%0], [%1], 16;"::"r"(d),"l"(s)); }
__device__ __forceinline__ void cp4(uint32_t d, const void* s){
    asm volatile("cp.async.ca.shared.global [%0], [%1], 4;"::"r"(d),"l"(s)); }
#define CP_COMMIT() asm volatile("cp.async.commit_group;":::"memory")
#define CP_WAIT1()  asm volatile("cp.async.wait_group 1;":::"memory")
#define CP_WAIT2()  asm volatile("cp.async.wait_group 2;":::"memory")

#define HMMA(c,a,b0,b1) asm volatile( \
    "mma.sync.aligned.m16n8k16.row.col.f32.f16.f16.f32 " \
    "{%0,%1,%2,%3},{%4,%5,%6,%7},{%8,%9},{%0,%1,%2,%3};" \
    : "+f"((c)[0]),"+f"((c)[1]),"+f"((c)[2]),"+f"((c)[3]) \
    : "r"((a)[0]),"r"((a)[1]),"r"((a)[2]),"r"((a)[3]),"r"(b0),"r"(b1))

#define LDSM4(R0,R1,R2,R3,A) asm volatile( \
    "ldmatrix.sync.aligned.m8n8.x4.shared.b16 {%0,%1,%2,%3}, [%4];" \
    : "=r"(R0),"=r"(R1),"=r"(R2),"=r"(R3) : "r"(A))

extern __shared__ char dynsm[];

// ---------------- mask expand ----------------
__global__ void mask_kernel(const unsigned char* __restrict__ mraw){
    __shared__ int flag;
    if (threadIdx.x==0) flag=0;
    __syncthreads();
    int any=0;
    for (int i=threadIdx.x;i<NROWS;i+=blockDim.x) any |= (mraw[i]!=0);
    if (any) atomicOr(&flag,1);
    __syncthreads();
    const int bytemode=flag; const int* mi=(const int*)mraw;
    for (int i=threadIdx.x;i<NROWS;i+=blockDim.x){
        bool m = bytemode ? (mraw[i]!=0) : (mi[i]!=0);
        g_maskbias[i] = m ? -1e30f : 0.0f;
    }
}

// ---------------- fp32 -> fp16 converts ----------------
__global__ void convert_inputs(const float* __restrict__ q, const float* __restrict__ k,
                               const float* __restrict__ v){
    int idx = blockIdx.x*blockDim.x + threadIdx.x;
    if (idx >= 3*(NE/4)) return;
    int seg = idx / (NE/4), off = idx % (NE/4);
    const float* src = seg==0? q : (seg==1? k : v);
    float4 x = ((const float4*)src)[off];
    __half2* d = (__half2*)(g_Xh + (size_t)seg*NE + (size_t)off*4);
    d[0] = __floats2half2_rn(x.x, x.y);
    d[1] = __floats2half2_rn(x.z, x.w);
}
__global__ void convert_weights(const float* __restrict__ wq, const float* __restrict__ wk,
                                const float* __restrict__ wv, const float* __restrict__ wo){
    int idx = blockIdx.x*blockDim.x + threadIdx.x;
    if (idx >= 4*(WE/4)) return;
    int seg = idx / (WE/4), off = idx % (WE/4);
    const float* src = seg==0?wq:(seg==1?wk:(seg==2?wv:wo));
    float4 x = ((const float4*)src)[off];
    __half2* d = (__half2*)(g_Wh + (size_t)seg*WE + (size_t)off*4);
    d[0] = __floats2half2_rn(x.x, x.y);
    d[1] = __floats2half2_rn(x.z, x.w);
}

// ================= fp16 GEMM, ldmatrix + 3-stage pipeline =================
// CTA 128x128, 8 warps of 64x32, BK=32, 3 stages.
// SMEM: X stages @ st*10240 (128 rows x 40 halves); W @ 30720 + st*10240. total 61440.
__device__ __forceinline__ void hg_load(uint32_t sb, const __half* X, const __half* W,
                                        int rowbase, int colbase, int kt, int tid, int st){
#pragma unroll
    for (int p=0;p<2;p++){
        int idx = tid + p*256;
        int r = idx>>2, ch = idx&3;
        cp16(sb + st*10240 + r*80 + ch*16, X + (size_t)(rowbase+r)*EMB + kt*32 + ch*8);
        cp16(sb + 30720 + st*10240 + r*80 + ch*16, W + (size_t)(colbase+r)*EMB + kt*32 + ch*8);
    }
}

__global__ __launch_bounds__(256,2)
void hgemm(const __half* __restrict__ X, const __half* __restrict__ W,
           const float* __restrict__ bias, void* __restrict__ out, int mode)
{
    const uint32_t sb = smem_u32(dynsm);
    const int tid=threadIdx.x, wid=tid>>5, lane=tid&31;
    const int g = lane>>2, q4 = lane&3;
    const int wm = wid&1, wn = wid>>1;
    const int quad = lane>>3;
    const int rowbase = blockIdx.y*128, colbase = blockIdx.x*128;

    // ldmatrix lane offsets
    const uint32_t aoff = (uint32_t)((wm*64 + (lane&15))*80 + (lane>>4)*16);
    const uint32_t boff = (uint32_t)((wn*32 + ((quad>>1)&1)*8 + (lane&7))*80 + (quad&1)*16);

    hg_load(sb, X, W, rowbase, colbase, 0, tid, 0); CP_COMMIT();
    hg_load(sb, X, W, rowbase, colbase, 1, tid, 1); CP_COMMIT();
    hg_load(sb, X, W, rowbase, colbase, 2, tid, 2); CP_COMMIT();

    float acc[4][4][4];
#pragma unroll
    for (int mi=0;mi<4;mi++)
#pragma unroll
        for (int ji=0;ji<4;ji++)
#pragma unroll
            for (int x=0;x<4;x++) acc[mi][ji][x]=0.f;

    int st = 0;
    for (int kt=0;kt<16;kt++){
        CP_WAIT2();
        __syncthreads();
        const uint32_t xa = sb + st*10240 + aoff;
        const uint32_t wa = sb + 30720 + st*10240 + boff;
#pragma unroll
        for (int c=0;c<2;c++){
            uint32_t a[4][4], bf[4][2];
#pragma unroll
            for (int mi=0;mi<4;mi++)
                LDSM4(a[mi][0],a[mi][1],a[mi][2],a[mi][3], xa + mi*1280 + c*32);
#pragma unroll
            for (int jp=0;jp<2;jp++)
                LDSM4(bf[2*jp][0],bf[2*jp][1],bf[2*jp+1][0],bf[2*jp+1][1], wa + jp*1280 + c*32);
#pragma unroll
            for (int mi=0;mi<4;mi++)
#pragma unroll
                for (int ji=0;ji<4;ji++)
                    HMMA(acc[mi][ji], a[mi], bf[ji][0], bf[ji][1]);
        }
        __syncthreads();
        if (kt < 13) hg_load(sb, X, W, rowbase, colbase, kt+3, tid, st);
        CP_COMMIT();
        st = (st==2)? 0 : st+1;
    }

    // epilogue
#pragma unroll
    for (int mi=0;mi<4;mi++){
        const int r0 = rowbase + wm*64 + mi*16 + g;
#pragma unroll
        for (int ji=0;ji<4;ji++){
            const int e = colbase + wn*32 + ji*8 + 2*q4;
            float2 bv = *(const float2*)(bias + e);
#pragma unroll
            for (int half=0; half<2; half++){
                const int r = r0 + half*8;
                float vx = acc[mi][ji][2*half+0] + bv.x;
                float vy = acc[mi][ji][2*half+1] + bv.y;
                if (mode==1){
                    float2 v; v.x=vx; v.y=vy;
                    *(float2*)((float*)out + (size_t)r*EMB + e) = v;
                } else {
                    int bb_=r>>12, s=r&(SEQ-1), hh=e>>6, d=e&(HD-1);
                    if (mode==0){
                        *(__half2*)((__half*)out + (((size_t)(bb_*NH+hh))*SEQ+s)*HD + d)
                            = __floats2half2_rn(vx, vy);
                    } else {
                        __half* o = (__half*)out + ((size_t)(bb_*NH+hh))*HD*SEQ;
                        o[(size_t)d*SEQ + s]     = __float2half_rn(vx);
                        o[(size_t)(d+1)*SEQ + s] = __float2half_rn(vy);
                    }
                }
            }
        }
    }
}

// ---------------- RoPE ----------------
__global__ void rope_h(){
    const int total=BHTOT*SEQ*(HD/2);
    int gid=blockIdx.x*blockDim.x+threadIdx.x;
    if (gid>=total) return;
    int i=gid&31, row=gid>>5, s=row&(SEQ-1);
    float inv=powf(10000.0f, -(float)i/32.0f);
    float sn, cs; sincosf((float)s*inv,&sn,&cs);
    size_t base=(size_t)row*HD;
    const float qs=0.125f*1.44269504f;
    float q0=__half2float(g_Qh[base+i]), q1=__half2float(g_Qh[base+i+32]);
    g_Qh[base+i]    = __float2half_rn(qs*(q0*cs-q1*sn));
    g_Qh[base+i+32] = __float2half_rn(qs*(q1*cs+q0*sn));
    float k0=__half2float(g_Kh[base+i]), k1=__half2float(g_Kh[base+i+32]);
    g_Kh[base+i]    = __float2half_rn(k0*cs-k1*sn);
    g_Kh[base+i+32] = __float2half_rn(k1*cs+k0*sn);
}

// ================= fp16 flash attention, ldmatrix =================
#define FQ_B   1024
#define FK_B   19456
#define FV_B   37888
#define FSMEM  56320

__device__ __forceinline__ void f_loadK(uint32_t sb, int bh, int t, int tid){
#pragma unroll
    for (int p=0;p<2;p++){
        int idx = tid + p*256;
        int r = idx>>3, ch = idx&7;
        cp16(sb + FK_B + (t&1)*9216 + r*144 + ch*16,
             g_Kh + ((size_t)bh*SEQ + t*64 + r)*HD + ch*8);
    }
}
__device__ __forceinline__ void f_loadV(uint32_t sb, int bh, int t, int tid){
#pragma unroll
    for (int p=0;p<2;p++){
        int idx = tid + p*256;
        int r = idx>>3, ch = idx&7;
        cp16(sb + FV_B + (t&1)*9216 + r*144 + ch*16,
             g_Vt + ((size_t)bh*HD + r)*SEQ + t*64 + ch*8);
    }
}
__device__ __forceinline__ void f_loadMB(uint32_t sb, int b, int t, int tid){
    if (tid < 64) cp4(sb + (t&1)*256 + tid*4, g_maskbias + b*SEQ + t*64 + tid);
}

__global__ __launch_bounds__(256,2) void flash_h()
{
    const float* smF = (const float*)dynsm;
    const uint32_t* smU = (const uint32_t*)dynsm;
    const uint32_t sb = smem_u32(dynsm);
    const int tid=threadIdx.x, wid=tid>>5, lane=tid&31;
    const int g = lane>>2, q4 = lane&3;
    const int quad = lane>>3;
    const int bh=blockIdx.y, b=bh>>3, h=bh&7;
    const int q0=blockIdx.x*128;

    // ldmatrix lane offset for K/V tiles (stride 144B): row-in-tile + k-half
    const uint32_t lofs = (uint32_t)((((quad>>1)&1)*8 + (lane&7))*144 + (quad&1)*16);

#pragma unroll
    for (int p=0;p<4;p++){
        int idx = tid + p*256;
        int r = idx>>3, ch = idx&7;
        cp16(sb + FQ_B + r*144 + ch*16, g_Qh + ((size_t)bh*SEQ + q0 + r)*HD + ch*8);
    }
    f_loadK(sb, bh, 0, tid); f_loadV(sb, bh, 0, tid); f_loadMB(sb, b, 0, tid);
    CP_COMMIT();
    f_loadK(sb, bh, 1, tid); f_loadV(sb, bh, 1, tid); f_loadMB(sb, b, 1, tid);
    CP_COMMIT();

    float o[8][4];
#pragma unroll
    for (int j=0;j<8;j++)
#pragma unroll
        for (int x=0;x<4;x++) o[j][x]=0.f;
    float rs0=0.f, rs1=0.f;
    uint32_t qf[4][4];

    for (int i=0;i<64;i++){
        const int buf = i&1;
        CP_WAIT1();
        __syncthreads();

        if (i==0){
            const uint32_t* Qu = smU + FQ_B/4;
#pragma unroll
            for (int c=0;c<4;c++){
                const uint32_t* qp = Qu + (wid*16+g)*36 + c*8 + q4;
                qf[c][0]=qp[0]; qf[c][1]=qp[8*36]; qf[c][2]=qp[4]; qf[c][3]=qp[8*36+4];
            }
        }

        // ---- S = Q K^T ----
        float s[8][4];
#pragma unroll
        for (int j=0;j<8;j++)
#pragma unroll
            for (int x=0;x<4;x++) s[j][x]=0.f;
        const uint32_t kb = sb + FK_B + buf*9216 + lofs;
#pragma unroll
        for (int c=0;c<4;c++){
            uint32_t kf[8][2];
#pragma unroll
            for (int jp=0;jp<4;jp++)
                LDSM4(kf[2*jp][0],kf[2*jp][1],kf[2*jp+1][0],kf[2*jp+1][1], kb + jp*2304 + c*32);
#pragma unroll
            for (int j=0;j<8;j++)
                HMMA(s[j], qf[c], kf[j][0], kf[j][1]);
        }

        // ---- softmax ----
        const float* mbF = smF + buf*64;
        uint32_t pp[8][2];
#pragma unroll
        for (int j=0;j<8;j++){
            float2 mb2 = *(const float2*)(mbF + j*8 + 2*q4);
            float p0 = ex2f(s[j][0] + mb2.x);
            float p1 = ex2f(s[j][1] + mb2.y);
            float p2 = ex2f(s[j][2] + mb2.x);
            float p3 = ex2f(s[j][3] + mb2.y);
            rs0 += p0+p1; rs1 += p2+p3;
            pp[j][0] = h2pack(p0, p1);
            pp[j][1] = h2pack(p2, p3);
        }

        // ---- O += P V ----
        const uint32_t vb = sb + FV_B + buf*9216 + lofs;
#pragma unroll
        for (int c=0;c<4;c++){
            uint32_t A[4] = {pp[2*c][0], pp[2*c][1], pp[2*c+1][0], pp[2*c+1][1]};
            uint32_t vf[8][2];
#pragma unroll
            for (int jp=0;jp<4;jp++)
                LDSM4(vf[2*jp][0],vf[2*jp][1],vf[2*jp+1][0],vf[2*jp+1][1], vb + jp*2304 + c*32);
#pragma unroll
            for (int jn=0;jn<8;jn++)
                HMMA(o[jn], A, vf[jn][0], vf[jn][1]);
        }
        __syncthreads();

        if (i < 62){ f_loadK(sb, bh, i+2, tid); f_loadV(sb, bh, i+2, tid); f_loadMB(sb, b, i+2, tid); }
        CP_COMMIT();
    }

    // ---- epilogue ----
    rs0 += __shfl_xor_sync(0xFFFFFFFF, rs0, 1);
    rs0 += __shfl_xor_sync(0xFFFFFFFF, rs0, 2);
    rs1 += __shfl_xor_sync(0xFFFFFFFF, rs1, 1);
    rs1 += __shfl_xor_sync(0xFFFFFFFF, rs1, 2);
    const float inv0 = 1.0f/rs0, inv1 = 1.0f/rs1;
    const int row0 = q0 + wid*16 + g;
    __half* d0 = g_ctxh + ((size_t)(b*SEQ + row0  ))*EMB + h*HD;
    __half* d1 = g_ctxh + ((size_t)(b*SEQ + row0+8))*EMB + h*HD;
#pragma unroll
    for (int jn=0;jn<8;jn++){
        *(__half2*)(d0 + jn*8 + 2*q4) = __floats2half2_rn(o[jn][0]*inv0, o[jn][1]*inv0);
        *(__half2*)(d1 + jn*8 + 2*q4) = __floats2half2_rn(o[jn][2]*inv1, o[jn][3]*inv1);
    }
}

// ---------------- launch ----------------
extern "C" void kernel_launch(void* const* d_in, const int* in_sizes, int n_in,
                              void* d_out, int out_size)
{
    const float* query=(const float*)d_in[0];
    const float* key_ =(const float*)d_in[1];
    const float* value=(const float*)d_in[2];
    const float* Wq=(const float*)d_in[3];  const float* bq=(const float*)d_in[4];
    const float* Wk=(const float*)d_in[5];  const float* bk=(const float*)d_in[6];
    const float* Wv=(const float*)d_in[7];  const float* bv=(const float*)d_in[8];
    const float* Wo=(const float*)d_in[9];  const float* bo=(const float*)d_in[10];
    const unsigned char* mask=(const unsigned char*)d_in[11];

    __half *Xh,*Wh,*Qh,*Kh,*Vt,*Ch;
    cudaGetSymbolAddress((void**)&Xh, g_Xh);
    cudaGetSymbolAddress((void**)&Wh, g_Wh);
    cudaGetSymbolAddress((void**)&Qh, g_Qh);
    cudaGetSymbolAddress((void**)&Kh, g_Kh);
    cudaGetSymbolAddress((void**)&Vt, g_Vt);
    cudaGetSymbolAddress((void**)&Ch, g_ctxh);

    cudaFuncSetAttribute(flash_h, cudaFuncAttributeMaxDynamicSharedMemorySize, FSMEM);
    cudaFuncSetAttribute(hgemm,   cudaFuncAttributeMaxDynamicSharedMemorySize, 61440);

    mask_kernel<<<1,256>>>(mask);
    convert_inputs <<<(3*(NE/4)+255)/256,256>>>(query, key_, value);
    convert_weights<<<(4*(WE/4)+255)/256,256>>>(Wq, Wk, Wv, Wo);

    dim3 ggrid(EMB/128, NROWS/128);
    hgemm<<<ggrid,256,61440>>>(Xh,        Wh,        bq, Qh, 0);
    hgemm<<<ggrid,256,61440>>>(Xh + NE,   Wh + WE,   bk, Kh, 0);
    hgemm<<<ggrid,256,61440>>>(Xh + 2*NE, Wh + 2*WE, bv, Vt, 2);

    const int rope_total=BHTOT*SEQ*(HD/2);
    rope_h<<<(rope_total+255)/256,256>>>();

    flash_h<<<dim3(SEQ/128, BHTOT), 256, FSMEM>>>();

    hgemm<<<ggrid,256,61440>>>(Ch, Wh + 3*WE, bo, d_out, 1);
}

// round 9
// speedup vs baseline: 2.0361x; 1.1464x over previous
#include <cuda_runtime.h>
#include <cuda_fp16.h>
#include <math.h>
#include <stdint.h>

#define BATCH 2
#define SEQ   4096
#define EMB   512
#define NH    8
#define HD    64
#define BHTOT (BATCH*NH)
#define NROWS (BATCH*SEQ)
#define NE    (NROWS*EMB)
#define WE    (EMB*EMB)

// ---------------- fp16 scratch ----------------
__device__ __half g_Xh[3*NE];
__device__ __half g_Wh[4*WE];
__device__ __half g_Qh[BHTOT*SEQ*HD];    // rope'd, scaled by 0.125*log2e
__device__ __half g_Kh[BHTOT*SEQ*HD];
__device__ __half g_Vt[BHTOT*HD*SEQ];    // transposed [bh][hd][s]
__device__ __half g_ctxh[NROWS*EMB];
__device__ __half g_maskh[NROWS];        // 0 or -inf (fp16)

// ---------------- helpers ----------------
__device__ __forceinline__ uint32_t smem_u32(const void* p){
    uint32_t a; asm("{ .reg .u64 t; cvta.to.shared.u64 t, %1; cvt.u32.u64 %0, t; }":"=r"(a):"l"(p)); return a;
}
__device__ __forceinline__ uint32_t h2pack(float lo, float hi){
    uint32_t d; asm("cvt.rn.f16x2.f32 %0, %1, %2;":"=r"(d):"f"(hi),"f"(lo)); return d;
}
__device__ __forceinline__ uint32_t hadd2(uint32_t a, uint32_t b){
    uint32_t d; asm("add.rn.f16x2 %0, %1, %2;":"=r"(d):"r"(a),"r"(b)); return d;
}
__device__ __forceinline__ uint32_t ex2h2(uint32_t a){
    uint32_t d; asm("ex2.approx.f16x2 %0, %1;":"=r"(d):"r"(a)); return d;
}
__device__ __forceinline__ void cp16(uint32_t d, const void* s){
    asm volatile("cp.async.cg.shared.global [%0], [%1], 16;"::"r"(d),"l"(s)); }
__device__ __forceinline__ void cp4(uint32_t d, const void* s){
    asm volatile("cp.async.ca.shared.global [%0], [%1], 4;"::"r"(d),"l"(s)); }
#define CP_COMMIT() asm volatile("cp.async.commit_group;":::"memory")
#define CP_WAIT1()  asm volatile("cp.async.wait_group 1;":::"memory")
#define CP_WAIT2()  asm volatile("cp.async.wait_group 2;":::"memory")

#define HMMA(c,a,b0,b1) asm volatile( \
    "mma.sync.aligned.m16n8k16.row.col.f32.f16.f16.f32 " \
    "{%0,%1,%2,%3},{%4,%5,%6,%7},{%8,%9},{%0,%1,%2,%3};" \
    : "+f"((c)[0]),"+f"((c)[1]),"+f"((c)[2]),"+f"((c)[3]) \
    : "r"((a)[0]),"r"((a)[1]),"r"((a)[2]),"r"((a)[3]),"r"(b0),"r"(b1))

#define LDSM4(R0,R1,R2,R3,A) asm volatile( \
    "ldmatrix.sync.aligned.m8n8.x4.shared.b16 {%0,%1,%2,%3}, [%4];" \
    : "=r"(R0),"=r"(R1),"=r"(R2),"=r"(R3) : "r"(A))

extern __shared__ char dynsm[];

// ---------------- mask expand (fp16 bias) ----------------
__global__ void mask_kernel(const unsigned char* __restrict__ mraw){
    __shared__ int flag;
    if (threadIdx.x==0) flag=0;
    __syncthreads();
    int any=0;
    for (int i=threadIdx.x;i<NROWS;i+=blockDim.x) any |= (mraw[i]!=0);
    if (any) atomicOr(&flag,1);
    __syncthreads();
    const int bytemode=flag; const int* mi=(const int*)mraw;
    for (int i=threadIdx.x;i<NROWS;i+=blockDim.x){
        bool m = bytemode ? (mraw[i]!=0) : (mi[i]!=0);
        g_maskh[i] = __float2half(m ? -1e30f : 0.0f);   // -> -inf / +0
    }
}

// ---------------- fp32 -> fp16 converts ----------------
__global__ void convert_inputs(const float* __restrict__ q, const float* __restrict__ k,
                               const float* __restrict__ v){
    int idx = blockIdx.x*blockDim.x + threadIdx.x;
    if (idx >= 3*(NE/4)) return;
    int seg = idx / (NE/4), off = idx % (NE/4);
    const float* src = seg==0? q : (seg==1? k : v);
    float4 x = ((const float4*)src)[off];
    __half2* d = (__half2*)(g_Xh + (size_t)seg*NE + (size_t)off*4);
    d[0] = __floats2half2_rn(x.x, x.y);
    d[1] = __floats2half2_rn(x.z, x.w);
}
__global__ void convert_weights(const float* __restrict__ wq, const float* __restrict__ wk,
                                const float* __restrict__ wv, const float* __restrict__ wo){
    int idx = blockIdx.x*blockDim.x + threadIdx.x;
    if (idx >= 4*(WE/4)) return;
    int seg = idx / (WE/4), off = idx % (WE/4);
    const float* src = seg==0?wq:(seg==1?wk:(seg==2?wv:wo));
    float4 x = ((const float4*)src)[off];
    __half2* d = (__half2*)(g_Wh + (size_t)seg*WE + (size_t)off*4);
    d[0] = __floats2half2_rn(x.x, x.y);
    d[1] = __floats2half2_rn(x.z, x.w);
}

// ================= fp16 GEMM: 4-stage pipeline, single sync =================
// CTA 128x128, 8 warps of 64x32, BK=32.
// SMEM: X stages @ st*10240 (128 x 40 halves); W @ 40960 + st*10240. total 81920.
__device__ __forceinline__ void hg_load(uint32_t sb, const __half* X, const __half* W,
                                        int rowbase, int colbase, int kt, int tid, int st){
#pragma unroll
    for (int p=0;p<2;p++){
        int idx = tid + p*256;
        int r = idx>>2, ch = idx&3;
        cp16(sb + st*10240 + r*80 + ch*16, X + (size_t)(rowbase+r)*EMB + kt*32 + ch*8);
        cp16(sb + 40960 + st*10240 + r*80 + ch*16, W + (size_t)(colbase+r)*EMB + kt*32 + ch*8);
    }
}

__global__ __launch_bounds__(256,2)
void hgemm(const __half* __restrict__ X, const __half* __restrict__ W,
           const float* __restrict__ bias, void* __restrict__ out, int mode)
{
    const uint32_t sb = smem_u32(dynsm);
    const int tid=threadIdx.x, wid=tid>>5, lane=tid&31;
    const int g = lane>>2, q4 = lane&3;
    const int wm = wid&1, wn = wid>>1;
    const int quad = lane>>3;
    const int rowbase = blockIdx.y*128, colbase = blockIdx.x*128;

    const uint32_t aoff = (uint32_t)((wm*64 + (lane&15))*80 + (lane>>4)*16);
    const uint32_t boff = (uint32_t)((wn*32 + ((quad>>1)&1)*8 + (lane&7))*80 + (quad&1)*16);

    hg_load(sb, X, W, rowbase, colbase, 0, tid, 0); CP_COMMIT();
    hg_load(sb, X, W, rowbase, colbase, 1, tid, 1); CP_COMMIT();
    hg_load(sb, X, W, rowbase, colbase, 2, tid, 2); CP_COMMIT();

    float acc[4][4][4];
#pragma unroll
    for (int mi=0;mi<4;mi++)
#pragma unroll
        for (int ji=0;ji<4;ji++)
#pragma unroll
            for (int x=0;x<4;x++) acc[mi][ji][x]=0.f;

    int st = 0;
    for (int kt=0;kt<16;kt++){
        CP_WAIT2();
        __syncthreads();
        const uint32_t xa = sb + st*10240 + aoff;
        const uint32_t wa = sb + 40960 + st*10240 + boff;
#pragma unroll
        for (int c=0;c<2;c++){
            uint32_t a[4][4], bf[4][2];
#pragma unroll
            for (int mi=0;mi<4;mi++)
                LDSM4(a[mi][0],a[mi][1],a[mi][2],a[mi][3], xa + mi*1280 + c*32);
#pragma unroll
            for (int jp=0;jp<2;jp++)
                LDSM4(bf[2*jp][0],bf[2*jp][1],bf[2*jp+1][0],bf[2*jp+1][1], wa + jp*1280 + c*32);
#pragma unroll
            for (int mi=0;mi<4;mi++)
#pragma unroll
                for (int ji=0;ji<4;ji++)
                    HMMA(acc[mi][ji], a[mi], bf[ji][0], bf[ji][1]);
        }
        // 4-stage: prefetch target (kt+3)%4 == (kt-1)%4, fully consumed before
        // every warp passed this iteration's top barrier -> no second sync.
        if (kt < 13) hg_load(sb, X, W, rowbase, colbase, kt+3, tid, (st+3)&3);
        CP_COMMIT();
        st = (st+1)&3;
    }

    // epilogue
#pragma unroll
    for (int mi=0;mi<4;mi++){
        const int r0 = rowbase + wm*64 + mi*16 + g;
#pragma unroll
        for (int ji=0;ji<4;ji++){
            const int e = colbase + wn*32 + ji*8 + 2*q4;
            float2 bv = *(const float2*)(bias + e);
#pragma unroll
            for (int half=0; half<2; half++){
                const int r = r0 + half*8;
                float vx = acc[mi][ji][2*half+0] + bv.x;
                float vy = acc[mi][ji][2*half+1] + bv.y;
                if (mode==1){
                    float2 v; v.x=vx; v.y=vy;
                    *(float2*)((float*)out + (size_t)r*EMB + e) = v;
                } else {
                    int bb_=r>>12, s=r&(SEQ-1), hh=e>>6, d=e&(HD-1);
                    if (mode==0){
                        *(__half2*)((__half*)out + (((size_t)(bb_*NH+hh))*SEQ+s)*HD + d)
                            = __floats2half2_rn(vx, vy);
                    } else {
                        __half* o = (__half*)out + ((size_t)(bb_*NH+hh))*HD*SEQ;
                        o[(size_t)d*SEQ + s]     = __float2half_rn(vx);
                        o[(size_t)(d+1)*SEQ + s] = __float2half_rn(vy);
                    }
                }
            }
        }
    }
}

// ---------------- RoPE ----------------
__global__ void rope_h(){
    const int total=BHTOT*SEQ*(HD/2);
    int gid=blockIdx.x*blockDim.x+threadIdx.x;
    if (gid>=total) return;
    int i=gid&31, row=gid>>5, s=row&(SEQ-1);
    float inv=powf(10000.0f, -(float)i/32.0f);
    float sn, cs; sincosf((float)s*inv,&sn,&cs);
    size_t base=(size_t)row*HD;
    const float qs=0.125f*1.44269504f;
    float q0=__half2float(g_Qh[base+i]), q1=__half2float(g_Qh[base+i+32]);
    g_Qh[base+i]    = __float2half_rn(qs*(q0*cs-q1*sn));
    g_Qh[base+i+32] = __float2half_rn(qs*(q1*cs+q0*sn));
    float k0=__half2float(g_Kh[base+i]), k1=__half2float(g_Kh[base+i+32]);
    g_Kh[base+i]    = __float2half_rn(k0*cs-k1*sn);
    g_Kh[base+i+32] = __float2half_rn(k1*cs+k0*sn);
}

// ================= fp16 flash attention: 3-buf, single sync, h2 softmax ======
// SMEM: mb@0 (3 x 128B), Q@1024 (128x144), K@19456 (3x9216), V@47104 (3x9216).
#define FQ_B   1024
#define FK_B   19456
#define FV_B   47104
#define FSMEM  74752
#define ONESH2 0x3C003C00u

__device__ __forceinline__ void f_loadK(uint32_t sb, int bh, int t, int tid, int st){
#pragma unroll
    for (int p=0;p<2;p++){
        int idx = tid + p*256;
        int r = idx>>3, ch = idx&7;
        cp16(sb + FK_B + st*9216 + r*144 + ch*16,
             g_Kh + ((size_t)bh*SEQ + t*64 + r)*HD + ch*8);
    }
}
__device__ __forceinline__ void f_loadV(uint32_t sb, int bh, int t, int tid, int st){
#pragma unroll
    for (int p=0;p<2;p++){
        int idx = tid + p*256;
        int r = idx>>3, ch = idx&7;
        cp16(sb + FV_B + st*9216 + r*144 + ch*16,
             g_Vt + ((size_t)bh*HD + r)*SEQ + t*64 + ch*8);
    }
}
__device__ __forceinline__ void f_loadMB(uint32_t sb, int b, int t, int tid, int st){
    if (tid < 32) cp4(sb + st*128 + tid*4, g_maskh + b*SEQ + t*64 + tid*2);
}

__global__ __launch_bounds__(256,2) void flash_h()
{
    const uint32_t sb = smem_u32(dynsm);
    const uint32_t* smU = (const uint32_t*)dynsm;
    const int tid=threadIdx.x, wid=tid>>5, lane=tid&31;
    const int g = lane>>2, q4 = lane&3;
    const int quad = lane>>3;
    const int bh=blockIdx.y, b=bh>>3, h=bh&7;
    const int q0=blockIdx.x*128;

    const uint32_t lofs = (uint32_t)((((quad>>1)&1)*8 + (lane&7))*144 + (quad&1)*16);

#pragma unroll
    for (int p=0;p<4;p++){
        int idx = tid + p*256;
        int r = idx>>3, ch = idx&7;
        cp16(sb + FQ_B + r*144 + ch*16, g_Qh + ((size_t)bh*SEQ + q0 + r)*HD + ch*8);
    }
    f_loadK(sb, bh, 0, tid, 0); f_loadV(sb, bh, 0, tid, 0); f_loadMB(sb, b, 0, tid, 0);
    CP_COMMIT();
    f_loadK(sb, bh, 1, tid, 1); f_loadV(sb, bh, 1, tid, 1); f_loadMB(sb, b, 1, tid, 1);
    CP_COMMIT();

    float o[8][4];
#pragma unroll
    for (int j=0;j<8;j++)
#pragma unroll
        for (int x=0;x<4;x++) o[j][x]=0.f;
    float racc[4] = {0.f,0.f,0.f,0.f};   // rowsum via ones-HMMA
    uint32_t qf[4][4];

    // Q fragments once (group0 complete after wait<=1)
    CP_WAIT1();
    __syncthreads();
    {
        const uint32_t* Qu = smU + FQ_B/4;
#pragma unroll
        for (int c=0;c<4;c++){
            const uint32_t* qp = Qu + (wid*16+g)*36 + c*8 + q4;
            qf[c][0]=qp[0]; qf[c][1]=qp[8*36]; qf[c][2]=qp[4]; qf[c][3]=qp[8*36+4];
        }
    }

    int cb = 0;
    for (int i=0;i<64;i++){
        CP_WAIT1();
        __syncthreads();

        // ---- S = Q K^T ----
        float s[8][4];
#pragma unroll
        for (int j=0;j<8;j++)
#pragma unroll
            for (int x=0;x<4;x++) s[j][x]=0.f;
        const uint32_t kb = sb + FK_B + cb*9216 + lofs;
#pragma unroll
        for (int c=0;c<4;c++){
            uint32_t kf[8][2];
#pragma unroll
            for (int jp=0;jp<4;jp++)
                LDSM4(kf[2*jp][0],kf[2*jp][1],kf[2*jp+1][0],kf[2*jp+1][1], kb + jp*2304 + c*32);
#pragma unroll
            for (int j=0;j<8;j++)
                HMMA(s[j], qf[c], kf[j][0], kf[j][1]);
        }

        // ---- softmax in f16x2: p = 2^(s + mb) ----
        const uint32_t* mbU = smU + cb*32;    // 128B buf
        uint32_t pp[8][2];
#pragma unroll
        for (int j=0;j<8;j++){
            uint32_t mb2u = mbU[j*4 + q4];
            pp[j][0] = ex2h2(hadd2(h2pack(s[j][0], s[j][1]), mb2u));
            pp[j][1] = ex2h2(hadd2(h2pack(s[j][2], s[j][3]), mb2u));
        }

        // ---- O += P V ; rowsum += P·1 ----
        const uint32_t vb = sb + FV_B + cb*9216 + lofs;
#pragma unroll
        for (int c=0;c<4;c++){
            uint32_t A[4] = {pp[2*c][0], pp[2*c][1], pp[2*c+1][0], pp[2*c+1][1]};
            uint32_t vf[8][2];
#pragma unroll
            for (int jp=0;jp<4;jp++)
                LDSM4(vf[2*jp][0],vf[2*jp][1],vf[2*jp+1][0],vf[2*jp+1][1], vb + jp*2304 + c*32);
#pragma unroll
            for (int jn=0;jn<8;jn++)
                HMMA(o[jn], A, vf[jn][0], vf[jn][1]);
            HMMA(racc, A, ONESH2, ONESH2);
        }

        // 3-buf: prefetch target (cb+2)%3 was consumed at tile i-1; the top
        // barrier of this iteration proves all warps left it -> no second sync.
        if (i < 62){
            const int pb = (cb+2>2)? cb-1 : cb+2;
            f_loadK(sb, bh, i+2, tid, pb);
            f_loadV(sb, bh, i+2, tid, pb);
            f_loadMB(sb, b, i+2, tid, pb);
        }
        CP_COMMIT();
        cb = (cb+1==3)? 0 : cb+1;
    }

    // ---- epilogue (racc[0]=rowsum rows g, racc[2]=rows g+8; no shuffles) ----
    const float inv0 = 1.0f/racc[0], inv1 = 1.0f/racc[2];
    const int row0 = q0 + wid*16 + g;
    __half* d0 = g_ctxh + ((size_t)(b*SEQ + row0  ))*EMB + h*HD;
    __half* d1 = g_ctxh + ((size_t)(b*SEQ + row0+8))*EMB + h*HD;
#pragma unroll
    for (int jn=0;jn<8;jn++){
        *(__half2*)(d0 + jn*8 + 2*q4) = __floats2half2_rn(o[jn][0]*inv0, o[jn][1]*inv0);
        *(__half2*)(d1 + jn*8 + 2*q4) = __floats2half2_rn(o[jn][2]*inv1, o[jn][3]*inv1);
    }
}

// ---------------- launch ----------------
extern "C" void kernel_launch(void* const* d_in, const int* in_sizes, int n_in,
                              void* d_out, int out_size)
{
    const float* query=(const float*)d_in[0];
    const float* key_ =(const float*)d_in[1];
    const float* value=(const float*)d_in[2];
    const float* Wq=(const float*)d_in[3];  const float* bq=(const float*)d_in[4];
    const float* Wk=(const float*)d_in[5];  const float* bk=(const float*)d_in[6];
    const float* Wv=(const float*)d_in[7];  const float* bv=(const float*)d_in[8];
    const float* Wo=(const float*)d_in[9];  const float* bo=(const float*)d_in[10];
    const unsigned char* mask=(const unsigned char*)d_in[11];

    __half *Xh,*Wh,*Qh,*Kh,*Vt,*Ch;
    cudaGetSymbolAddress((void**)&Xh, g_Xh);
    cudaGetSymbolAddress((void**)&Wh, g_Wh);
    cudaGetSymbolAddress((void**)&Qh, g_Qh);
    cudaGetSymbolAddress((void**)&Kh, g_Kh);
    cudaGetSymbolAddress((void**)&Vt, g_Vt);
    cudaGetSymbolAddress((void**)&Ch, g_ctxh);

    cudaFuncSetAttribute(flash_h, cudaFuncAttributeMaxDynamicSharedMemorySize, FSMEM);
    cudaFuncSetAttribute(hgemm,   cudaFuncAttributeMaxDynamicSharedMemorySize, 81920);

    mask_kernel<<<1,256>>>(mask);
    convert_inputs <<<(3*(NE/4)+255)/256,256>>>(query, key_, value);
    convert_weights<<<(4*(WE/4)+255)/256,256>>>(Wq, Wk, Wv, Wo);

    dim3 ggrid(EMB/128, NROWS/128);
    hgemm<<<ggrid,256,81920>>>(Xh,        Wh,        bq, Qh, 0);
    hgemm<<<ggrid,256,81920>>>(Xh + NE,   Wh + WE,   bk, Kh, 0);
    hgemm<<<ggrid,256,81920>>>(Xh + 2*NE, Wh + 2*WE, bv, Vt, 2);

    const int rope_total=BHTOT*SEQ*(HD/2);
    rope_h<<<(rope_total+255)/256,256>>>();

    flash_h<<<dim3(SEQ/128, BHTOT), 256, FSMEM>>>();

    hgemm<<<ggrid,256,81920>>>(Ch, Wh + 3*WE, bo, d_out, 1);
}

// round 10
// speedup vs baseline: 2.1094x; 1.0360x over previous
#include <cuda_runtime.h>
#include <cuda_fp16.h>
#include <math.h>
#include <stdint.h>

#define BATCH 2
#define SEQ   4096
#define EMB   512
#define NH    8
#define HD    64
#define BHTOT (BATCH*NH)
#define NROWS (BATCH*SEQ)
#define NE    (NROWS*EMB)
#define WE    (EMB*EMB)

// ---------------- scratch ----------------
__device__ __half g_Xh[3*NE];
__device__ __half g_Wh[4*WE];
__device__ __half g_Qh[BHTOT*SEQ*HD];
__device__ __half g_Kh[BHTOT*SEQ*HD];
__device__ __half g_Vt[BHTOT*HD*SEQ];    // [bh][hd][s]
__device__ __half g_ctxh[NROWS*EMB];
__device__ __half g_maskh[NROWS];        // 0 or -inf
__device__ int    g_tileskip[BATCH*64];  // 1 if all 64 keys of tile masked
__device__ float2 g_rope[SEQ*32];        // (cos, sin)

// ---------------- helpers ----------------
__device__ __forceinline__ uint32_t smem_u32(const void* p){
    uint32_t a; asm("{ .reg .u64 t; cvta.to.shared.u64 t, %1; cvt.u32.u64 %0, t; }":"=r"(a):"l"(p)); return a;
}
__device__ __forceinline__ uint32_t h2pack(float lo, float hi){
    uint32_t d; asm("cvt.rn.f16x2.f32 %0, %1, %2;":"=r"(d):"f"(hi),"f"(lo)); return d;
}
__device__ __forceinline__ uint32_t hadd2(uint32_t a, uint32_t b){
    uint32_t d; asm("add.rn.f16x2 %0, %1, %2;":"=r"(d):"r"(a),"r"(b)); return d;
}
__device__ __forceinline__ uint32_t ex2h2(uint32_t a){
    uint32_t d; asm("ex2.approx.f16x2 %0, %1;":"=r"(d):"r"(a)); return d;
}
__device__ __forceinline__ void cp16(uint32_t d, const void* s){
    asm volatile("cp.async.cg.shared.global [%0], [%1], 16;"::"r"(d),"l"(s)); }
__device__ __forceinline__ void cp4(uint32_t d, const void* s){
    asm volatile("cp.async.ca.shared.global [%0], [%1], 4;"::"r"(d),"l"(s)); }
#define CP_COMMIT() asm volatile("cp.async.commit_group;":::"memory")
#define CP_WAIT1()  asm volatile("cp.async.wait_group 1;":::"memory")

#define HMMA(c,a,b0,b1) asm volatile( \
    "mma.sync.aligned.m16n8k16.row.col.f32.f16.f16.f32 " \
    "{%0,%1,%2,%3},{%4,%5,%6,%7},{%8,%9},{%0,%1,%2,%3};" \
    : "+f"((c)[0]),"+f"((c)[1]),"+f"((c)[2]),"+f"((c)[3]) \
    : "r"((a)[0]),"r"((a)[1]),"r"((a)[2]),"r"((a)[3]),"r"(b0),"r"(b1))

#define LDSM4(R0,R1,R2,R3,A) asm volatile( \
    "ldmatrix.sync.aligned.m8n8.x4.shared.b16 {%0,%1,%2,%3}, [%4];" \
    : "=r"(R0),"=r"(R1),"=r"(R2),"=r"(R3) : "r"(A))

extern __shared__ char dynsm[];

// ---------------- mask expand + per-tile skip flags ----------------
__global__ void mask_kernel(const unsigned char* __restrict__ mraw){
    __shared__ int flag;
    if (threadIdx.x==0) flag=0;
    __syncthreads();
    int any=0;
    for (int i=threadIdx.x;i<NROWS;i+=blockDim.x) any |= (mraw[i]!=0);
    if (any) atomicOr(&flag,1);
    __syncthreads();
    const int bytemode=flag; const int* mi=(const int*)mraw;
    for (int i=threadIdx.x;i<NROWS;i+=blockDim.x){
        bool m = bytemode ? (mraw[i]!=0) : (mi[i]!=0);
        g_maskh[i] = __float2half(m ? -1e30f : 0.0f);
    }
    if (threadIdx.x < BATCH*64){
        int b = threadIdx.x>>6, t = threadIdx.x&63;
        int all = 1;
        for (int j=0;j<64;j++){
            int i = b*SEQ + t*64 + j;
            bool m = bytemode ? (mraw[i]!=0) : (mi[i]!=0);
            all &= (int)m;
        }
        g_tileskip[threadIdx.x] = all;
    }
}

// ---------------- fused converts + rope table ----------------
#define NIN (3*(NE/4))
#define NW  (4*(WE/4))
#define NT  (SEQ*32)
__global__ void convert_all(const float* __restrict__ q, const float* __restrict__ k,
                            const float* __restrict__ v, const float* __restrict__ wq,
                            const float* __restrict__ wk, const float* __restrict__ wv,
                            const float* __restrict__ wo){
    int idx = blockIdx.x*blockDim.x + threadIdx.x;
    if (idx < NIN){
        int seg = idx / (NE/4), off = idx % (NE/4);
        const float* src = seg==0? q : (seg==1? k : v);
        float4 x = ((const float4*)src)[off];
        __half2* d = (__half2*)(g_Xh + (size_t)seg*NE + (size_t)off*4);
        d[0] = __floats2half2_rn(x.x, x.y);
        d[1] = __floats2half2_rn(x.z, x.w);
    } else if (idx < NIN+NW){
        int j = idx - NIN;
        int seg = j / (WE/4), off = j % (WE/4);
        const float* src = seg==0?wq:(seg==1?wk:(seg==2?wv:wo));
        float4 x = ((const float4*)src)[off];
        __half2* d = (__half2*)(g_Wh + (size_t)seg*WE + (size_t)off*4);
        d[0] = __floats2half2_rn(x.x, x.y);
        d[1] = __floats2half2_rn(x.z, x.w);
    } else if (idx < NIN+NW+NT){
        int j = idx - NIN - NW;
        int i = j & 31, s = j >> 5;
        float inv = exp2f(-(float)i * 0.41524101186097f);   // log2(10000)/32
        float sn, cs; __sincosf((float)s*inv, &sn, &cs);
        g_rope[j] = make_float2(cs, sn);
    }
}

// ================= fp16 GEMM core: BK=64, 3-stage, single sync =================
// CTA 128x128, 8 warps of 64x32. SMEM: X stages @ st*18432 (128 x 72 halves);
// W @ 55296 + st*18432. Total 110592.
#define HG_SMEM 110592

__device__ __forceinline__ void hg_load(uint32_t sb, const __half* X, const __half* W,
                                        int rowbase, int colbase, int kt, int tid, int st){
#pragma unroll
    for (int p=0;p<4;p++){
        int idx = tid + p*256;            // 0..1023
        int r = idx>>3, ch = idx&7;
        cp16(sb + st*18432 + r*144 + ch*16, X + (size_t)(rowbase+r)*EMB + kt*64 + ch*8);
        cp16(sb + 55296 + st*18432 + r*144 + ch*16, W + (size_t)(colbase+r)*EMB + kt*64 + ch*8);
    }
}

__device__ __forceinline__ void hgemm_core(const __half* __restrict__ X,
                                           const __half* __restrict__ W,
                                           const float* __restrict__ bias,
                                           void* __restrict__ out, int mode)
{
    const uint32_t sb = smem_u32(dynsm);
    const int tid=threadIdx.x, wid=tid>>5, lane=tid&31;
    const int g = lane>>2, q4 = lane&3;
    const int wm = wid&1, wn = wid>>1;
    const int quad = lane>>3;
    const int rowbase = blockIdx.y*128, colbase = blockIdx.x*128;

    const uint32_t aoff = (uint32_t)((wm*64 + (lane&15))*144 + (lane>>4)*16);
    const uint32_t boff = (uint32_t)((wn*32 + ((quad>>1)&1)*8 + (lane&7))*144 + (quad&1)*16);

    hg_load(sb, X, W, rowbase, colbase, 0, tid, 0); CP_COMMIT();
    hg_load(sb, X, W, rowbase, colbase, 1, tid, 1); CP_COMMIT();

    float acc[4][4][4];
#pragma unroll
    for (int mi=0;mi<4;mi++)
#pragma unroll
        for (int ji=0;ji<4;ji++)
#pragma unroll
            for (int x=0;x<4;x++) acc[mi][ji][x]=0.f;

    int st = 0;
    for (int kt=0;kt<8;kt++){            // BK=64 per iteration
        CP_WAIT1();
        __syncthreads();
        const uint32_t xa = sb + st*18432 + aoff;
        const uint32_t wa = sb + 55296 + st*18432 + boff;
#pragma unroll
        for (int c=0;c<4;c++){
            uint32_t a[4][4], bf[4][2];
#pragma unroll
            for (int mi=0;mi<4;mi++)
                LDSM4(a[mi][0],a[mi][1],a[mi][2],a[mi][3], xa + mi*2304 + c*32);
#pragma unroll
            for (int jp=0;jp<2;jp++)
                LDSM4(bf[2*jp][0],bf[2*jp][1],bf[2*jp+1][0],bf[2*jp+1][1], wa + jp*2304 + c*32);
#pragma unroll
            for (int mi=0;mi<4;mi++)
#pragma unroll
                for (int ji=0;ji<4;ji++)
                    HMMA(acc[mi][ji], a[mi], bf[ji][0], bf[ji][1]);
        }
        // prefetch into stage consumed last iteration (top barrier protects it)
        if (kt < 6){
            const int pb = (st+2>2)? st-1 : st+2;
            hg_load(sb, X, W, rowbase, colbase, kt+2, tid, pb);
        }
        CP_COMMIT();
        st = (st+1==3)? 0 : st+1;
    }

    // epilogue
#pragma unroll
    for (int mi=0;mi<4;mi++){
        const int r0 = rowbase + wm*64 + mi*16 + g;
#pragma unroll
        for (int ji=0;ji<4;ji++){
            const int e = colbase + wn*32 + ji*8 + 2*q4;
            float2 bv = *(const float2*)(bias + e);
#pragma unroll
            for (int half=0; half<2; half++){
                const int r = r0 + half*8;
                float vx = acc[mi][ji][2*half+0] + bv.x;
                float vy = acc[mi][ji][2*half+1] + bv.y;
                if (mode==1){
                    float2 v; v.x=vx; v.y=vy;
                    *(float2*)((float*)out + (size_t)r*EMB + e) = v;
                } else {
                    int bb_=r>>12, s=r&(SEQ-1), hh=e>>6, d=e&(HD-1);
                    if (mode==0){
                        *(__half2*)((__half*)out + (((size_t)(bb_*NH+hh))*SEQ+s)*HD + d)
                            = __floats2half2_rn(vx, vy);
                    } else {
                        __half* o = (__half*)out + ((size_t)(bb_*NH+hh))*HD*SEQ;
                        o[(size_t)d*SEQ + s]     = __float2half_rn(vx);
                        o[(size_t)(d+1)*SEQ + s] = __float2half_rn(vy);
                    }
                }
            }
        }
    }
}

__global__ __launch_bounds__(256,2)
void hgemm_qkv(const float* __restrict__ bq, const float* __restrict__ bk,
               const float* __restrict__ bv){
    const int z = blockIdx.z;
    const float* bias = (z==0)? bq : ((z==1)? bk : bv);
    void* out = (z==0)? (void*)g_Qh : ((z==1)? (void*)g_Kh : (void*)g_Vt);
    hgemm_core(g_Xh + (size_t)z*NE, g_Wh + (size_t)z*WE, bias, out, (z==2)?2:0);
}

__global__ __launch_bounds__(256,2)
void hgemm_one(const __half* __restrict__ X, const __half* __restrict__ W,
               const float* __restrict__ bias, void* __restrict__ out, int mode){
    hgemm_core(X, W, bias, out, mode);
}

// ---------------- RoPE (table-based) ----------------
__global__ void rope_h(){
    const int total=BHTOT*SEQ*(HD/2);
    int gid=blockIdx.x*blockDim.x+threadIdx.x;
    if (gid>=total) return;
    int i=gid&31, row=gid>>5, s=row&(SEQ-1);
    float2 t = g_rope[(s<<5)|i];
    const float cs=t.x, sn=t.y;
    size_t base=(size_t)row*HD;
    const float qs=0.125f*1.44269504f;
    float q0=__half2float(g_Qh[base+i]), q1=__half2float(g_Qh[base+i+32]);
    g_Qh[base+i]    = __float2half_rn(qs*(q0*cs-q1*sn));
    g_Qh[base+i+32] = __float2half_rn(qs*(q1*cs+q0*sn));
    float k0=__half2float(g_Kh[base+i]), k1=__half2float(g_Kh[base+i+32]);
    g_Kh[base+i]    = __float2half_rn(k0*cs-k1*sn);
    g_Kh[base+i+32] = __float2half_rn(k1*cs+k0*sn);
}

// ================= fp16 flash attention (R9 + tile skip) ======
// SMEM: mb@0 (3x128B), skipflags@512 (64 ints), Q@1024, K@19456 (3x9216), V@47104 (3x9216).
#define FQ_B   1024
#define FK_B   19456
#define FV_B   47104
#define FSMEM  74752
#define ONESH2 0x3C003C00u

__device__ __forceinline__ void f_loadK(uint32_t sb, int bh, int t, int tid, int st){
#pragma unroll
    for (int p=0;p<2;p++){
        int idx = tid + p*256;
        int r = idx>>3, ch = idx&7;
        cp16(sb + FK_B + st*9216 + r*144 + ch*16,
             g_Kh + ((size_t)bh*SEQ + t*64 + r)*HD + ch*8);
    }
}
__device__ __forceinline__ void f_loadV(uint32_t sb, int bh, int t, int tid, int st){
#pragma unroll
    for (int p=0;p<2;p++){
        int idx = tid + p*256;
        int r = idx>>3, ch = idx&7;
        cp16(sb + FV_B + st*9216 + r*144 + ch*16,
             g_Vt + ((size_t)bh*HD + r)*SEQ + t*64 + ch*8);
    }
}
__device__ __forceinline__ void f_loadMB(uint32_t sb, int b, int t, int tid, int st){
    if (tid < 32) cp4(sb + st*128 + tid*4, g_maskh + b*SEQ + t*64 + tid*2);
}

__global__ __launch_bounds__(256,2) void flash_h()
{
    const uint32_t sb = smem_u32(dynsm);
    const uint32_t* smU = (const uint32_t*)dynsm;
    const int tid=threadIdx.x, wid=tid>>5, lane=tid&31;
    const int g = lane>>2, q4 = lane&3;
    const int quad = lane>>3;
    const int bh=blockIdx.y, b=bh>>3, h=bh&7;
    const int q0=blockIdx.x*128;

    const uint32_t lofs = (uint32_t)((((quad>>1)&1)*8 + (lane&7))*144 + (quad&1)*16);

#pragma unroll
    for (int p=0;p<4;p++){
        int idx = tid + p*256;
        int r = idx>>3, ch = idx&7;
        cp16(sb + FQ_B + r*144 + ch*16, g_Qh + ((size_t)bh*SEQ + q0 + r)*HD + ch*8);
    }
    if (tid < 64) cp4(sb + 512 + tid*4, g_tileskip + b*64 + tid);
    f_loadK(sb, bh, 0, tid, 0); f_loadV(sb, bh, 0, tid, 0); f_loadMB(sb, b, 0, tid, 0);
    CP_COMMIT();
    f_loadK(sb, bh, 1, tid, 1); f_loadV(sb, bh, 1, tid, 1); f_loadMB(sb, b, 1, tid, 1);
    CP_COMMIT();

    float o[8][4];
#pragma unroll
    for (int j=0;j<8;j++)
#pragma unroll
        for (int x=0;x<4;x++) o[j][x]=0.f;
    float racc[4] = {0.f,0.f,0.f,0.f};
    uint32_t qf[4][4];

    CP_WAIT1();
    __syncthreads();
    {
        const uint32_t* Qu = smU + FQ_B/4;
#pragma unroll
        for (int c=0;c<4;c++){
            const uint32_t* qp = Qu + (wid*16+g)*36 + c*8 + q4;
            qf[c][0]=qp[0]; qf[c][1]=qp[8*36]; qf[c][2]=qp[4]; qf[c][3]=qp[8*36+4];
        }
    }

    int cb = 0;
    for (int i=0;i<64;i++){
        CP_WAIT1();
        __syncthreads();

        const int skip = ((const int*)dynsm)[128 + i];   // all-masked tile
        if (!skip){
            // ---- S = Q K^T ----
            float s[8][4];
#pragma unroll
            for (int j=0;j<8;j++)
#pragma unroll
                for (int x=0;x<4;x++) s[j][x]=0.f;
            const uint32_t kb = sb + FK_B + cb*9216 + lofs;
#pragma unroll
            for (int c=0;c<4;c++){
                uint32_t kf[8][2];
#pragma unroll
                for (int jp=0;jp<4;jp++)
                    LDSM4(kf[2*jp][0],kf[2*jp][1],kf[2*jp+1][0],kf[2*jp+1][1], kb + jp*2304 + c*32);
#pragma unroll
                for (int j=0;j<8;j++)
                    HMMA(s[j], qf[c], kf[j][0], kf[j][1]);
            }

            // ---- softmax in f16x2 ----
            const uint32_t* mbU = smU + cb*32;
            uint32_t pp[8][2];
#pragma unroll
            for (int j=0;j<8;j++){
                uint32_t mb2u = mbU[j*4 + q4];
                pp[j][0] = ex2h2(hadd2(h2pack(s[j][0], s[j][1]), mb2u));
                pp[j][1] = ex2h2(hadd2(h2pack(s[j][2], s[j][3]), mb2u));
            }

            // ---- O += P V ; rowsum += P·1 ----
            const uint32_t vb = sb + FV_B + cb*9216 + lofs;
#pragma unroll
            for (int c=0;c<4;c++){
                uint32_t A[4] = {pp[2*c][0], pp[2*c][1], pp[2*c+1][0], pp[2*c+1][1]};
                uint32_t vf[8][2];
#pragma unroll
                for (int jp=0;jp<4;jp++)
                    LDSM4(vf[2*jp][0],vf[2*jp][1],vf[2*jp+1][0],vf[2*jp+1][1], vb + jp*2304 + c*32);
#pragma unroll
                for (int jn=0;jn<8;jn++)
                    HMMA(o[jn], A, vf[jn][0], vf[jn][1]);
                HMMA(racc, A, ONESH2, ONESH2);
            }
        }

        if (i < 62){
            const int pb = (cb+2>2)? cb-1 : cb+2;
            f_loadK(sb, bh, i+2, tid, pb);
            f_loadV(sb, bh, i+2, tid, pb);
            f_loadMB(sb, b, i+2, tid, pb);
        }
        CP_COMMIT();
        cb = (cb+1==3)? 0 : cb+1;
    }

    // ---- epilogue ----
    const float inv0 = 1.0f/racc[0], inv1 = 1.0f/racc[2];
    const int row0 = q0 + wid*16 + g;
    __half* d0 = g_ctxh + ((size_t)(b*SEQ + row0  ))*EMB + h*HD;
    __half* d1 = g_ctxh + ((size_t)(b*SEQ + row0+8))*EMB + h*HD;
#pragma unroll
    for (int jn=0;jn<8;jn++){
        *(__half2*)(d0 + jn*8 + 2*q4) = __floats2half2_rn(o[jn][0]*inv0, o[jn][1]*inv0);
        *(__half2*)(d1 + jn*8 + 2*q4) = __floats2half2_rn(o[jn][2]*inv1, o[jn][3]*inv1);
    }
}

// ---------------- launch ----------------
extern "C" void kernel_launch(void* const* d_in, const int* in_sizes, int n_in,
                              void* d_out, int out_size)
{
    const float* query=(const float*)d_in[0];
    const float* key_ =(const float*)d_in[1];
    const float* value=(const float*)d_in[2];
    const float* Wq=(const float*)d_in[3];  const float* bq=(const float*)d_in[4];
    const float* Wk=(const float*)d_in[5];  const float* bk=(const float*)d_in[6];
    const float* Wv=(const float*)d_in[7];  const float* bv=(const float*)d_in[8];
    const float* Wo=(const float*)d_in[9];  const float* bo=(const float*)d_in[10];
    const unsigned char* mask=(const unsigned char*)d_in[11];

    __half *Wh,*Ch;
    cudaGetSymbolAddress((void**)&Wh, g_Wh);
    cudaGetSymbolAddress((void**)&Ch, g_ctxh);

    cudaFuncSetAttribute(flash_h,   cudaFuncAttributeMaxDynamicSharedMemorySize, FSMEM);
    cudaFuncSetAttribute(hgemm_qkv, cudaFuncAttributeMaxDynamicSharedMemorySize, HG_SMEM);
    cudaFuncSetAttribute(hgemm_one, cudaFuncAttributeMaxDynamicSharedMemorySize, HG_SMEM);

    mask_kernel<<<1,256>>>(mask);
    convert_all<<<(NIN+NW+NT+255)/256,256>>>(query, key_, value, Wq, Wk, Wv, Wo);

    hgemm_qkv<<<dim3(EMB/128, NROWS/128, 3),256,HG_SMEM>>>(bq, bk, bv);

    const int rope_total=BHTOT*SEQ*(HD/2);
    rope_h<<<(rope_total+255)/256,256>>>();

    flash_h<<<dim3(SEQ/128, BHTOT), 256, FSMEM>>>();

    hgemm_one<<<dim3(EMB/128, NROWS/128),256,HG_SMEM>>>(Ch, Wh + 3*(size_t)WE, bo, d_out, 1);
}

// round 11
// speedup vs baseline: 2.1508x; 1.0197x over previous
#include <cuda_runtime.h>
#include <cuda_fp16.h>
#include <math.h>
#include <stdint.h>

#define BATCH 2
#define SEQ   4096
#define EMB   512
#define NH    8
#define HD    64
#define BHTOT (BATCH*NH)
#define NROWS (BATCH*SEQ)
#define NE    (NROWS*EMB)
#define WE    (EMB*EMB)

// ---------------- scratch ----------------
__device__ __half g_Xh[3*NE];
__device__ __half g_Wh[4*WE];
__device__ __half g_Qh[BHTOT*SEQ*HD];    // [bh][s][hd]
__device__ __half g_Kh[BHTOT*SEQ*HD];    // [bh][s][hd]
__device__ __half g_Vh[BHTOT*SEQ*HD];    // [bh][s][hd] (plain; flash uses ldmatrix.trans)
__device__ __half g_ctxh[NROWS*EMB];
__device__ __half g_maskh[NROWS];        // 0 or -inf
__device__ int    g_tileskip[BATCH*64];
__device__ float2 g_rope[SEQ*32];        // (cos, sin)

// ---------------- helpers ----------------
__device__ __forceinline__ uint32_t smem_u32(const void* p){
    uint32_t a; asm("{ .reg .u64 t; cvta.to.shared.u64 t, %1; cvt.u32.u64 %0, t; }":"=r"(a):"l"(p)); return a;
}
__device__ __forceinline__ uint32_t h2pack(float lo, float hi){
    uint32_t d; asm("cvt.rn.f16x2.f32 %0, %1, %2;":"=r"(d):"f"(hi),"f"(lo)); return d;
}
__device__ __forceinline__ uint32_t hadd2(uint32_t a, uint32_t b){
    uint32_t d; asm("add.rn.f16x2 %0, %1, %2;":"=r"(d):"r"(a),"r"(b)); return d;
}
__device__ __forceinline__ uint32_t ex2h2(uint32_t a){
    uint32_t d; asm("ex2.approx.f16x2 %0, %1;":"=r"(d):"r"(a)); return d;
}
__device__ __forceinline__ void cp16(uint32_t d, const void* s){
    asm volatile("cp.async.cg.shared.global [%0], [%1], 16;"::"r"(d),"l"(s)); }
__device__ __forceinline__ void cp4(uint32_t d, const void* s){
    asm volatile("cp.async.ca.shared.global [%0], [%1], 4;"::"r"(d),"l"(s)); }
#define CP_COMMIT() asm volatile("cp.async.commit_group;":::"memory")
#define CP_WAIT1()  asm volatile("cp.async.wait_group 1;":::"memory")

#define HMMA(c,a,b0,b1) asm volatile( \
    "mma.sync.aligned.m16n8k16.row.col.f32.f16.f16.f32 " \
    "{%0,%1,%2,%3},{%4,%5,%6,%7},{%8,%9},{%0,%1,%2,%3};" \
    : "+f"((c)[0]),"+f"((c)[1]),"+f"((c)[2]),"+f"((c)[3]) \
    : "r"((a)[0]),"r"((a)[1]),"r"((a)[2]),"r"((a)[3]),"r"(b0),"r"(b1))

#define LDSM4(R0,R1,R2,R3,A) asm volatile( \
    "ldmatrix.sync.aligned.m8n8.x4.shared.b16 {%0,%1,%2,%3}, [%4];" \
    : "=r"(R0),"=r"(R1),"=r"(R2),"=r"(R3) : "r"(A))
#define LDSM4_T(R0,R1,R2,R3,A) asm volatile( \
    "ldmatrix.sync.aligned.m8n8.x4.trans.shared.b16 {%0,%1,%2,%3}, [%4];" \
    : "=r"(R0),"=r"(R1),"=r"(R2),"=r"(R3) : "r"(A))

extern __shared__ char dynsm[];

// ---------------- fused converts + rope table + mask ----------------
#define NIN (3*(NE/4))
#define NW  (4*(WE/4))
#define NT  (SEQ*32)
__global__ void convert_all(const float* __restrict__ q, const float* __restrict__ k,
                            const float* __restrict__ v, const float* __restrict__ wq,
                            const float* __restrict__ wk, const float* __restrict__ wv,
                            const float* __restrict__ wo, const unsigned char* __restrict__ mraw){
    if (blockIdx.x == gridDim.x-1){
        // mask expand (one block)
        __shared__ int flag;
        if (threadIdx.x==0) flag=0;
        __syncthreads();
        int any=0;
        for (int i=threadIdx.x;i<NROWS;i+=blockDim.x) any |= (mraw[i]!=0);
        if (any) atomicOr(&flag,1);
        __syncthreads();
        const int bytemode=flag; const int* mi=(const int*)mraw;
        for (int i=threadIdx.x;i<NROWS;i+=blockDim.x){
            bool m = bytemode ? (mraw[i]!=0) : (mi[i]!=0);
            g_maskh[i] = __float2half(m ? -1e30f : 0.0f);
        }
        if (threadIdx.x < BATCH*64){
            int b = threadIdx.x>>6, t = threadIdx.x&63;
            int all = 1;
            for (int j=0;j<64;j++){
                int i = b*SEQ + t*64 + j;
                bool m = bytemode ? (mraw[i]!=0) : (mi[i]!=0);
                all &= (int)m;
            }
            g_tileskip[threadIdx.x] = all;
        }
        return;
    }
    int idx = blockIdx.x*blockDim.x + threadIdx.x;
    if (idx < NIN){
        int seg = idx / (NE/4), off = idx % (NE/4);
        const float* src = seg==0? q : (seg==1? k : v);
        float4 x = ((const float4*)src)[off];
        __half2* d = (__half2*)(g_Xh + (size_t)seg*NE + (size_t)off*4);
        d[0] = __floats2half2_rn(x.x, x.y);
        d[1] = __floats2half2_rn(x.z, x.w);
    } else if (idx < NIN+NW){
        int j = idx - NIN;
        int seg = j / (WE/4), off = j % (WE/4);
        const float* src = seg==0?wq:(seg==1?wk:(seg==2?wv:wo));
        float4 x = ((const float4*)src)[off];
        __half2* d = (__half2*)(g_Wh + (size_t)seg*WE + (size_t)off*4);
        d[0] = __floats2half2_rn(x.x, x.y);
        d[1] = __floats2half2_rn(x.z, x.w);
    } else if (idx < NIN+NW+NT){
        int j = idx - NIN - NW;
        int i = j & 31, s = j >> 5;
        float inv = exp2f(-(float)i * 0.41524101186097f);
        float sn, cs; __sincosf((float)s*inv, &sn, &cs);
        g_rope[j] = make_float2(cs, sn);
    }
}

// ================= fp16 GEMM core: BK=64, 3-stage, single sync =================
#define HG_SMEM 110592

__device__ __forceinline__ void hg_load(uint32_t sb, const __half* X, const __half* W,
                                        int rowbase, int colbase, int kt, int tid, int st){
#pragma unroll
    for (int p=0;p<4;p++){
        int idx = tid + p*256;
        int r = idx>>3, ch = idx&7;
        cp16(sb + st*18432 + r*144 + ch*16, X + (size_t)(rowbase+r)*EMB + kt*64 + ch*8);
        cp16(sb + 55296 + st*18432 + r*144 + ch*16, W + (size_t)(colbase+r)*EMB + kt*64 + ch*8);
    }
}

__device__ __forceinline__ void hgemm_core(const __half* __restrict__ X,
                                           const __half* __restrict__ W,
                                           const float* __restrict__ bias,
                                           void* __restrict__ out, int mode)
{
    const uint32_t sb = smem_u32(dynsm);
    const int tid=threadIdx.x, wid=tid>>5, lane=tid&31;
    const int g = lane>>2, q4 = lane&3;
    const int wm = wid&1, wn = wid>>1;
    const int quad = lane>>3;
    const int rowbase = blockIdx.y*128, colbase = blockIdx.x*128;

    const uint32_t aoff = (uint32_t)((wm*64 + (lane&15))*144 + (lane>>4)*16);
    const uint32_t boff = (uint32_t)((wn*32 + ((quad>>1)&1)*8 + (lane&7))*144 + (quad&1)*16);

    hg_load(sb, X, W, rowbase, colbase, 0, tid, 0); CP_COMMIT();
    hg_load(sb, X, W, rowbase, colbase, 1, tid, 1); CP_COMMIT();

    float acc[4][4][4];
#pragma unroll
    for (int mi=0;mi<4;mi++)
#pragma unroll
        for (int ji=0;ji<4;ji++)
#pragma unroll
            for (int x=0;x<4;x++) acc[mi][ji][x]=0.f;

    int st = 0;
    for (int kt=0;kt<8;kt++){
        CP_WAIT1();
        __syncthreads();
        const uint32_t xa = sb + st*18432 + aoff;
        const uint32_t wa = sb + 55296 + st*18432 + boff;
#pragma unroll
        for (int c=0;c<4;c++){
            uint32_t a[4][4], bf[4][2];
#pragma unroll
            for (int mi=0;mi<4;mi++)
                LDSM4(a[mi][0],a[mi][1],a[mi][2],a[mi][3], xa + mi*2304 + c*32);
#pragma unroll
            for (int jp=0;jp<2;jp++)
                LDSM4(bf[2*jp][0],bf[2*jp][1],bf[2*jp+1][0],bf[2*jp+1][1], wa + jp*2304 + c*32);
#pragma unroll
            for (int mi=0;mi<4;mi++)
#pragma unroll
                for (int ji=0;ji<4;ji++)
                    HMMA(acc[mi][ji], a[mi], bf[ji][0], bf[ji][1]);
        }
        if (kt < 6){
            const int pb = (st+2>2)? st-1 : st+2;
            hg_load(sb, X, W, rowbase, colbase, kt+2, tid, pb);
        }
        CP_COMMIT();
        st = (st+1==3)? 0 : st+1;
    }

#pragma unroll
    for (int mi=0;mi<4;mi++){
        const int r0 = rowbase + wm*64 + mi*16 + g;
#pragma unroll
        for (int ji=0;ji<4;ji++){
            const int e = colbase + wn*32 + ji*8 + 2*q4;
            float2 bv = *(const float2*)(bias + e);
#pragma unroll
            for (int half=0; half<2; half++){
                const int r = r0 + half*8;
                float vx = acc[mi][ji][2*half+0] + bv.x;
                float vy = acc[mi][ji][2*half+1] + bv.y;
                if (mode==1){
                    float2 v; v.x=vx; v.y=vy;
                    *(float2*)((float*)out + (size_t)r*EMB + e) = v;
                } else {
                    int bb_=r>>12, s=r&(SEQ-1), hh=e>>6, d=e&(HD-1);
                    *(__half2*)((__half*)out + (((size_t)(bb_*NH+hh))*SEQ+s)*HD + d)
                        = __floats2half2_rn(vx, vy);
                }
            }
        }
    }
}

__global__ __launch_bounds__(256,2)
void hgemm_qkv(const float* __restrict__ bq, const float* __restrict__ bk,
               const float* __restrict__ bv){
    const int z = blockIdx.z;
    const float* bias = (z==0)? bq : ((z==1)? bk : bv);
    void* out = (z==0)? (void*)g_Qh : ((z==1)? (void*)g_Kh : (void*)g_Vh);
    hgemm_core(g_Xh + (size_t)z*NE, g_Wh + (size_t)z*WE, bias, out, 0);
}

__global__ __launch_bounds__(256,2)
void hgemm_one(const __half* __restrict__ X, const __half* __restrict__ W,
               const float* __restrict__ bias, void* __restrict__ out, int mode){
    hgemm_core(X, W, bias, out, mode);
}

// ---------------- RoPE (table, half2-vectorized: 2 pairs/thread) ----------------
__global__ void rope_h(){
    const int total=BHTOT*SEQ*16;
    int gid=blockIdx.x*blockDim.x+threadIdx.x;
    if (gid>=total) return;
    int i2=gid&15, row=gid>>4, s=row&(SEQ-1);
    float2 t0 = g_rope[(s<<5)|(2*i2)];
    float2 t1 = g_rope[(s<<5)|(2*i2+1)];
    const float qs=0.125f*1.44269504f;
    size_t base=(size_t)row*HD + 2*i2;

    __half2 qa = *(__half2*)(g_Qh+base), qb = *(__half2*)(g_Qh+base+32);
    float2 fa = __half22float2(qa), fb = __half22float2(qb);
    *(__half2*)(g_Qh+base)    = __floats2half2_rn(qs*(fa.x*t0.x - fb.x*t0.y), qs*(fa.y*t1.x - fb.y*t1.y));
    *(__half2*)(g_Qh+base+32) = __floats2half2_rn(qs*(fb.x*t0.x + fa.x*t0.y), qs*(fb.y*t1.x + fa.y*t1.y));

    __half2 ka = *(__half2*)(g_Kh+base), kb = *(__half2*)(g_Kh+base+32);
    float2 ga = __half22float2(ka), gb = __half22float2(kb);
    *(__half2*)(g_Kh+base)    = __floats2half2_rn(ga.x*t0.x - gb.x*t0.y, ga.y*t1.x - gb.y*t1.y);
    *(__half2*)(g_Kh+base+32) = __floats2half2_rn(gb.x*t0.x + ga.x*t0.y, gb.y*t1.x + ga.y*t1.y);
}

// ================= fp16 flash attention (V via ldmatrix.trans) ======
#define FQ_B   1024
#define FK_B   19456
#define FV_B   47104
#define FSMEM  74752
#define ONESH2 0x3C003C00u

__device__ __forceinline__ void f_loadK(uint32_t sb, int bh, int t, int tid, int st){
#pragma unroll
    for (int p=0;p<2;p++){
        int idx = tid + p*256;
        int r = idx>>3, ch = idx&7;
        cp16(sb + FK_B + st*9216 + r*144 + ch*16,
             g_Kh + ((size_t)bh*SEQ + t*64 + r)*HD + ch*8);
    }
}
__device__ __forceinline__ void f_loadV(uint32_t sb, int bh, int t, int tid, int st){
#pragma unroll
    for (int p=0;p<2;p++){
        int idx = tid + p*256;
        int r = idx>>3, ch = idx&7;
        cp16(sb + FV_B + st*9216 + r*144 + ch*16,
             g_Vh + ((size_t)bh*SEQ + t*64 + r)*HD + ch*8);
    }
}
__device__ __forceinline__ void f_loadMB(uint32_t sb, int b, int t, int tid, int st){
    if (tid < 32) cp4(sb + st*128 + tid*4, g_maskh + b*SEQ + t*64 + tid*2);
}

__global__ __launch_bounds__(256,2) void flash_h()
{
    const uint32_t sb = smem_u32(dynsm);
    const uint32_t* smU = (const uint32_t*)dynsm;
    const int tid=threadIdx.x, wid=tid>>5, lane=tid&31;
    const int g = lane>>2, q4 = lane&3;
    const int quad = lane>>3;
    const int bh=blockIdx.y, b=bh>>3, h=bh&7;
    const int q0=blockIdx.x*128;

    // K (non-trans): row = n-half*8 + lane&7, chunk = k-half
    const uint32_t lofs  = (uint32_t)((((quad>>1)&1)*8 + (lane&7))*144 + (quad&1)*16);
    // V (trans): row = k-half*8 + lane&7 (s-rows), chunk = n-half
    const uint32_t lofsv = (uint32_t)(((quad&1)*8 + (lane&7))*144 + ((quad>>1)&1)*16);

#pragma unroll
    for (int p=0;p<4;p++){
        int idx = tid + p*256;
        int r = idx>>3, ch = idx&7;
        cp16(sb + FQ_B + r*144 + ch*16, g_Qh + ((size_t)bh*SEQ + q0 + r)*HD + ch*8);
    }
    if (tid < 64) cp4(sb + 512 + tid*4, g_tileskip + b*64 + tid);
    f_loadK(sb, bh, 0, tid, 0); f_loadV(sb, bh, 0, tid, 0); f_loadMB(sb, b, 0, tid, 0);
    CP_COMMIT();
    f_loadK(sb, bh, 1, tid, 1); f_loadV(sb, bh, 1, tid, 1); f_loadMB(sb, b, 1, tid, 1);
    CP_COMMIT();

    float o[8][4];
#pragma unroll
    for (int j=0;j<8;j++)
#pragma unroll
        for (int x=0;x<4;x++) o[j][x]=0.f;
    float racc[4] = {0.f,0.f,0.f,0.f};
    uint32_t qf[4][4];

    CP_WAIT1();
    __syncthreads();
    {
        const uint32_t* Qu = smU + FQ_B/4;
#pragma unroll
        for (int c=0;c<4;c++){
            const uint32_t* qp = Qu + (wid*16+g)*36 + c*8 + q4;
            qf[c][0]=qp[0]; qf[c][1]=qp[8*36]; qf[c][2]=qp[4]; qf[c][3]=qp[8*36+4];
        }
    }

    int cb = 0;
    for (int i=0;i<64;i++){
        CP_WAIT1();
        __syncthreads();

        const int skip = ((const int*)dynsm)[128 + i];
        if (!skip){
            // ---- S = Q K^T ----
            float s[8][4];
#pragma unroll
            for (int j=0;j<8;j++)
#pragma unroll
                for (int x=0;x<4;x++) s[j][x]=0.f;
            const uint32_t kb = sb + FK_B + cb*9216 + lofs;
#pragma unroll
            for (int c=0;c<4;c++){
                uint32_t kf[8][2];
#pragma unroll
                for (int jp=0;jp<4;jp++)
                    LDSM4(kf[2*jp][0],kf[2*jp][1],kf[2*jp+1][0],kf[2*jp+1][1], kb + jp*2304 + c*32);
#pragma unroll
                for (int j=0;j<8;j++)
                    HMMA(s[j], qf[c], kf[j][0], kf[j][1]);
            }

            // ---- softmax in f16x2 ----
            const uint32_t* mbU = smU + cb*32;
            uint32_t pp[8][2];
#pragma unroll
            for (int j=0;j<8;j++){
                uint32_t mb2u = mbU[j*4 + q4];
                pp[j][0] = ex2h2(hadd2(h2pack(s[j][0], s[j][1]), mb2u));
                pp[j][1] = ex2h2(hadd2(h2pack(s[j][2], s[j][3]), mb2u));
            }

            // ---- O += P V (V loaded transposed); rowsum += P·1 ----
            const uint32_t vb = sb + FV_B + cb*9216 + lofsv;
#pragma unroll
            for (int c=0;c<4;c++){
                uint32_t A[4] = {pp[2*c][0], pp[2*c][1], pp[2*c+1][0], pp[2*c+1][1]};
                uint32_t vf[8][2];
#pragma unroll
                for (int jp=0;jp<4;jp++)
                    LDSM4_T(vf[2*jp][0],vf[2*jp][1],vf[2*jp+1][0],vf[2*jp+1][1], vb + c*2304 + jp*32);
#pragma unroll
                for (int jn=0;jn<8;jn++)
                    HMMA(o[jn], A, vf[jn][0], vf[jn][1]);
                HMMA(racc, A, ONESH2, ONESH2);
            }
        }

        if (i < 62){
            const int pb = (cb+2>2)? cb-1 : cb+2;
            f_loadK(sb, bh, i+2, tid, pb);
            f_loadV(sb, bh, i+2, tid, pb);
            f_loadMB(sb, b, i+2, tid, pb);
        }
        CP_COMMIT();
        cb = (cb+1==3)? 0 : cb+1;
    }

    // ---- epilogue ----
    const float inv0 = 1.0f/racc[0], inv1 = 1.0f/racc[2];
    const int row0 = q0 + wid*16 + g;
    __half* d0 = g_ctxh + ((size_t)(b*SEQ + row0  ))*EMB + h*HD;
    __half* d1 = g_ctxh + ((size_t)(b*SEQ + row0+8))*EMB + h*HD;
#pragma unroll
    for (int jn=0;jn<8;jn++){
        *(__half2*)(d0 + jn*8 + 2*q4) = __floats2half2_rn(o[jn][0]*inv0, o[jn][1]*inv0);
        *(__half2*)(d1 + jn*8 + 2*q4) = __floats2half2_rn(o[jn][2]*inv1, o[jn][3]*inv1);
    }
}

// ---------------- launch ----------------
extern "C" void kernel_launch(void* const* d_in, const int* in_sizes, int n_in,
                              void* d_out, int out_size)
{
    const float* query=(const float*)d_in[0];
    const float* key_ =(const float*)d_in[1];
    const float* value=(const float*)d_in[2];
    const float* Wq=(const float*)d_in[3];  const float* bq=(const float*)d_in[4];
    const float* Wk=(const float*)d_in[5];  const float* bk=(const float*)d_in[6];
    const float* Wv=(const float*)d_in[7];  const float* bv=(const float*)d_in[8];
    const float* Wo=(const float*)d_in[9];  const float* bo=(const float*)d_in[10];
    const unsigned char* mask=(const unsigned char*)d_in[11];

    __half *Wh,*Ch;
    cudaGetSymbolAddress((void**)&Wh, g_Wh);
    cudaGetSymbolAddress((void**)&Ch, g_ctxh);

    cudaFuncSetAttribute(flash_h,   cudaFuncAttributeMaxDynamicSharedMemorySize, FSMEM);
    cudaFuncSetAttribute(hgemm_qkv, cudaFuncAttributeMaxDynamicSharedMemorySize, HG_SMEM);
    cudaFuncSetAttribute(hgemm_one, cudaFuncAttributeMaxDynamicSharedMemorySize, HG_SMEM);

    convert_all<<<(NIN+NW+NT+255)/256 + 1,256>>>(query, key_, value, Wq, Wk, Wv, Wo, mask);

    hgemm_qkv<<<dim3(EMB/128, NROWS/128, 3),256,HG_SMEM>>>(bq, bk, bv);

    rope_h<<<(BHTOT*SEQ*16+255)/256,256>>>();

    flash_h<<<dim3(SEQ/128, BHTOT), 256, FSMEM>>>();

    hgemm_one<<<dim3(EMB/128, NROWS/128),256,HG_SMEM>>>(Ch, Wh + 3*(size_t)WE, bo, d_out, 1);
}

// round 12
// speedup vs baseline: 2.2272x; 1.0355x over previous
#include <cuda_runtime.h>
#include <cuda_fp16.h>
#include <math.h>
#include <stdint.h>

#define BATCH 2
#define SEQ   4096
#define EMB   512
#define NH    8
#define HD    64
#define BHTOT (BATCH*NH)
#define NROWS (BATCH*SEQ)
#define NE    (NROWS*EMB)
#define WE    (EMB*EMB)

// ---------------- scratch ----------------
__device__ __half g_Xh[3*NE];
__device__ __half g_Wh[4*WE];
__device__ __half g_Qh[BHTOT*SEQ*HD];    // [bh][s][hd]
__device__ __half g_Kh[BHTOT*SEQ*HD];    // [bh][s][hd]
__device__ __half g_Vh[BHTOT*SEQ*HD];    // [bh][s][hd]
__device__ __half g_ctxh[NROWS*EMB];
__device__ __half g_maskh[NROWS];        // 0 or -inf
__device__ int    g_tileskip[BATCH*64];
__device__ float2 g_rope[SEQ*32];        // (cos, sin)

// ---------------- helpers ----------------
__device__ __forceinline__ uint32_t smem_u32(const void* p){
    uint32_t a; asm("{ .reg .u64 t; cvta.to.shared.u64 t, %1; cvt.u32.u64 %0, t; }":"=r"(a):"l"(p)); return a;
}
__device__ __forceinline__ uint32_t h2pack(float lo, float hi){
    uint32_t d; asm("cvt.rn.f16x2.f32 %0, %1, %2;":"=r"(d):"f"(hi),"f"(lo)); return d;
}
__device__ __forceinline__ uint32_t hadd2(uint32_t a, uint32_t b){
    uint32_t d; asm("add.rn.f16x2 %0, %1, %2;":"=r"(d):"r"(a),"r"(b)); return d;
}
__device__ __forceinline__ uint32_t ex2h2(uint32_t a){
    uint32_t d; asm("ex2.approx.f16x2 %0, %1;":"=r"(d):"r"(a)); return d;
}
__device__ __forceinline__ void cp16(uint32_t d, const void* s){
    asm volatile("cp.async.cg.shared.global [%0], [%1], 16;"::"r"(d),"l"(s)); }
__device__ __forceinline__ void cp4(uint32_t d, const void* s){
    asm volatile("cp.async.ca.shared.global [%0], [%1], 4;"::"r"(d),"l"(s)); }
#define CP_COMMIT() asm volatile("cp.async.commit_group;":::"memory")
#define CP_WAIT1()  asm volatile("cp.async.wait_group 1;":::"memory")

#define HMMA(c,a,b0,b1) asm volatile( \
    "mma.sync.aligned.m16n8k16.row.col.f32.f16.f16.f32 " \
    "{%0,%1,%2,%3},{%4,%5,%6,%7},{%8,%9},{%0,%1,%2,%3};" \
    : "+f"((c)[0]),"+f"((c)[1]),"+f"((c)[2]),"+f"((c)[3]) \
    : "r"((a)[0]),"r"((a)[1]),"r"((a)[2]),"r"((a)[3]),"r"(b0),"r"(b1))

#define LDSM4(R0,R1,R2,R3,A) asm volatile( \
    "ldmatrix.sync.aligned.m8n8.x4.shared.b16 {%0,%1,%2,%3}, [%4];" \
    : "=r"(R0),"=r"(R1),"=r"(R2),"=r"(R3) : "r"(A))
#define LDSM4_T(R0,R1,R2,R3,A) asm volatile( \
    "ldmatrix.sync.aligned.m8n8.x4.trans.shared.b16 {%0,%1,%2,%3}, [%4];" \
    : "=r"(R0),"=r"(R1),"=r"(R2),"=r"(R3) : "r"(A))

extern __shared__ char dynsm[];

// ---------------- fused converts + rope table + mask ----------------
#define NIN (3*(NE/4))
#define NW  (4*(WE/4))
#define NT  (SEQ*32)
__global__ void convert_all(const float* __restrict__ q, const float* __restrict__ k,
                            const float* __restrict__ v, const float* __restrict__ wq,
                            const float* __restrict__ wk, const float* __restrict__ wv,
                            const float* __restrict__ wo, const unsigned char* __restrict__ mraw){
    if (blockIdx.x == gridDim.x-1){
        __shared__ int flag;
        if (threadIdx.x==0) flag=0;
        __syncthreads();
        int any=0;
        for (int i=threadIdx.x;i<NROWS;i+=blockDim.x) any |= (mraw[i]!=0);
        if (any) atomicOr(&flag,1);
        __syncthreads();
        const int bytemode=flag; const int* mi=(const int*)mraw;
        for (int i=threadIdx.x;i<NROWS;i+=blockDim.x){
            bool m = bytemode ? (mraw[i]!=0) : (mi[i]!=0);
            g_maskh[i] = __float2half(m ? -1e30f : 0.0f);
        }
        if (threadIdx.x < BATCH*64){
            int b = threadIdx.x>>6, t = threadIdx.x&63;
            int all = 1;
            for (int j=0;j<64;j++){
                int i = b*SEQ + t*64 + j;
                bool m = bytemode ? (mraw[i]!=0) : (mi[i]!=0);
                all &= (int)m;
            }
            g_tileskip[threadIdx.x] = all;
        }
        return;
    }
    int idx = blockIdx.x*blockDim.x + threadIdx.x;
    if (idx < NIN){
        int seg = idx / (NE/4), off = idx % (NE/4);
        const float* src = seg==0? q : (seg==1? k : v);
        float4 x = ((const float4*)src)[off];
        __half2* d = (__half2*)(g_Xh + (size_t)seg*NE + (size_t)off*4);
        d[0] = __floats2half2_rn(x.x, x.y);
        d[1] = __floats2half2_rn(x.z, x.w);
    } else if (idx < NIN+NW){
        int j = idx - NIN;
        int seg = j / (WE/4), off = j % (WE/4);
        const float* src = seg==0?wq:(seg==1?wk:(seg==2?wv:wo));
        float4 x = ((const float4*)src)[off];
        __half2* d = (__half2*)(g_Wh + (size_t)seg*WE + (size_t)off*4);
        d[0] = __floats2half2_rn(x.x, x.y);
        d[1] = __floats2half2_rn(x.z, x.w);
    } else if (idx < NIN+NW+NT){
        int j = idx - NIN - NW;
        int i = j & 31, s = j >> 5;
        float inv = exp2f(-(float)i * 0.41524101186097f);
        float sn, cs; __sincosf((float)s*inv, &sn, &cs);
        g_rope[j] = make_float2(cs, sn);
    }
}

// ================= fp16 GEMM core (unchanged from R11) =================
#define HG_SMEM 110592

__device__ __forceinline__ void hg_load(uint32_t sb, const __half* X, const __half* W,
                                        int rowbase, int colbase, int kt, int tid, int st){
#pragma unroll
    for (int p=0;p<4;p++){
        int idx = tid + p*256;
        int r = idx>>3, ch = idx&7;
        cp16(sb + st*18432 + r*144 + ch*16, X + (size_t)(rowbase+r)*EMB + kt*64 + ch*8);
        cp16(sb + 55296 + st*18432 + r*144 + ch*16, W + (size_t)(colbase+r)*EMB + kt*64 + ch*8);
    }
}

__device__ __forceinline__ void hgemm_core(const __half* __restrict__ X,
                                           const __half* __restrict__ W,
                                           const float* __restrict__ bias,
                                           void* __restrict__ out, int mode)
{
    const uint32_t sb = smem_u32(dynsm);
    const int tid=threadIdx.x, wid=tid>>5, lane=tid&31;
    const int g = lane>>2, q4 = lane&3;
    const int wm = wid&1, wn = wid>>1;
    const int quad = lane>>3;
    const int rowbase = blockIdx.y*128, colbase = blockIdx.x*128;

    const uint32_t aoff = (uint32_t)((wm*64 + (lane&15))*144 + (lane>>4)*16);
    const uint32_t boff = (uint32_t)((wn*32 + ((quad>>1)&1)*8 + (lane&7))*144 + (quad&1)*16);

    hg_load(sb, X, W, rowbase, colbase, 0, tid, 0); CP_COMMIT();
    hg_load(sb, X, W, rowbase, colbase, 1, tid, 1); CP_COMMIT();

    float acc[4][4][4];
#pragma unroll
    for (int mi=0;mi<4;mi++)
#pragma unroll
        for (int ji=0;ji<4;ji++)
#pragma unroll
            for (int x=0;x<4;x++) acc[mi][ji][x]=0.f;

    int st = 0;
    for (int kt=0;kt<8;kt++){
        CP_WAIT1();
        __syncthreads();
        const uint32_t xa = sb + st*18432 + aoff;
        const uint32_t wa = sb + 55296 + st*18432 + boff;
#pragma unroll
        for (int c=0;c<4;c++){
            uint32_t a[4][4], bf[4][2];
#pragma unroll
            for (int mi=0;mi<4;mi++)
                LDSM4(a[mi][0],a[mi][1],a[mi][2],a[mi][3], xa + mi*2304 + c*32);
#pragma unroll
            for (int jp=0;jp<2;jp++)
                LDSM4(bf[2*jp][0],bf[2*jp][1],bf[2*jp+1][0],bf[2*jp+1][1], wa + jp*2304 + c*32);
#pragma unroll
            for (int mi=0;mi<4;mi++)
#pragma unroll
                for (int ji=0;ji<4;ji++)
                    HMMA(acc[mi][ji], a[mi], bf[ji][0], bf[ji][1]);
        }
        if (kt < 6){
            const int pb = (st+2>2)? st-1 : st+2;
            hg_load(sb, X, W, rowbase, colbase, kt+2, tid, pb);
        }
        CP_COMMIT();
        st = (st+1==3)? 0 : st+1;
    }

#pragma unroll
    for (int mi=0;mi<4;mi++){
        const int r0 = rowbase + wm*64 + mi*16 + g;
#pragma unroll
        for (int ji=0;ji<4;ji++){
            const int e = colbase + wn*32 + ji*8 + 2*q4;
            float2 bv = *(const float2*)(bias + e);
#pragma unroll
            for (int half=0; half<2; half++){
                const int r = r0 + half*8;
                float vx = acc[mi][ji][2*half+0] + bv.x;
                float vy = acc[mi][ji][2*half+1] + bv.y;
                if (mode==1){
                    float2 v; v.x=vx; v.y=vy;
                    *(float2*)((float*)out + (size_t)r*EMB + e) = v;
                } else {
                    int bb_=r>>12, s=r&(SEQ-1), hh=e>>6, d=e&(HD-1);
                    *(__half2*)((__half*)out + (((size_t)(bb_*NH+hh))*SEQ+s)*HD + d)
                        = __floats2half2_rn(vx, vy);
                }
            }
        }
    }
}

__global__ __launch_bounds__(256,2)
void hgemm_qkv(const float* __restrict__ bq, const float* __restrict__ bk,
               const float* __restrict__ bv){
    const int z = blockIdx.z;
    const float* bias = (z==0)? bq : ((z==1)? bk : bv);
    void* out = (z==0)? (void*)g_Qh : ((z==1)? (void*)g_Kh : (void*)g_Vh);
    hgemm_core(g_Xh + (size_t)z*NE, g_Wh + (size_t)z*WE, bias, out, 0);
}

__global__ __launch_bounds__(256,2)
void hgemm_one(const __half* __restrict__ X, const __half* __restrict__ W,
               const float* __restrict__ bias, void* __restrict__ out, int mode){
    hgemm_core(X, W, bias, out, mode);
}

// ---------------- RoPE (table, half2-vectorized) ----------------
__global__ void rope_h(){
    const int total=BHTOT*SEQ*16;
    int gid=blockIdx.x*blockDim.x+threadIdx.x;
    if (gid>=total) return;
    int i2=gid&15, row=gid>>4, s=row&(SEQ-1);
    float2 t0 = g_rope[(s<<5)|(2*i2)];
    float2 t1 = g_rope[(s<<5)|(2*i2+1)];
    const float qs=0.125f*1.44269504f;
    size_t base=(size_t)row*HD + 2*i2;

    __half2 qa = *(__half2*)(g_Qh+base), qb = *(__half2*)(g_Qh+base+32);
    float2 fa = __half22float2(qa), fb = __half22float2(qb);
    *(__half2*)(g_Qh+base)    = __floats2half2_rn(qs*(fa.x*t0.x - fb.x*t0.y), qs*(fa.y*t1.x - fb.y*t1.y));
    *(__half2*)(g_Qh+base+32) = __floats2half2_rn(qs*(fb.x*t0.x + fa.x*t0.y), qs*(fb.y*t1.x + fa.y*t1.y));

    __half2 ka = *(__half2*)(g_Kh+base), kb = *(__half2*)(g_Kh+base+32);
    float2 ga = __half22float2(ka), gb = __half22float2(kb);
    *(__half2*)(g_Kh+base)    = __floats2half2_rn(ga.x*t0.x - gb.x*t0.y, ga.y*t1.x - gb.y*t1.y);
    *(__half2*)(g_Kh+base+32) = __floats2half2_rn(gb.x*t0.x + ga.x*t0.y, gb.y*t1.x + ga.y*t1.y);
}

// ================= fp16 flash attention: 4 warps x 32 q-rows ======
#define FQ_B   1024
#define FK_B   19456
#define FV_B   47104
#define FSMEM  74752
#define ONESH2 0x3C003C00u

__device__ __forceinline__ void f_loadK(uint32_t sb, int bh, int t, int tid, int st){
#pragma unroll
    for (int p=0;p<4;p++){
        int idx = tid + p*128;
        int r = idx>>3, ch = idx&7;
        cp16(sb + FK_B + st*9216 + r*144 + ch*16,
             g_Kh + ((size_t)bh*SEQ + t*64 + r)*HD + ch*8);
    }
}
__device__ __forceinline__ void f_loadV(uint32_t sb, int bh, int t, int tid, int st){
#pragma unroll
    for (int p=0;p<4;p++){
        int idx = tid + p*128;
        int r = idx>>3, ch = idx&7;
        cp16(sb + FV_B + st*9216 + r*144 + ch*16,
             g_Vh + ((size_t)bh*SEQ + t*64 + r)*HD + ch*8);
    }
}
__device__ __forceinline__ void f_loadMB(uint32_t sb, int b, int t, int tid, int st){
    if (tid < 32) cp4(sb + st*128 + tid*4, g_maskh + b*SEQ + t*64 + tid*2);
}

__global__ __launch_bounds__(128,2) void flash_h()
{
    const uint32_t sb = smem_u32(dynsm);
    const uint32_t* smU = (const uint32_t*)dynsm;
    const int tid=threadIdx.x, wid=tid>>5, lane=tid&31;
    const int g = lane>>2, q4 = lane&3;
    const int quad = lane>>3;
    const int bh=blockIdx.y, b=bh>>3, h=bh&7;
    const int q0=blockIdx.x*128;

    const uint32_t lofs  = (uint32_t)((((quad>>1)&1)*8 + (lane&7))*144 + (quad&1)*16);
    const uint32_t lofsv = (uint32_t)(((quad&1)*8 + (lane&7))*144 + ((quad>>1)&1)*16);

#pragma unroll
    for (int p=0;p<8;p++){
        int idx = tid + p*128;
        int r = idx>>3, ch = idx&7;
        cp16(sb + FQ_B + r*144 + ch*16, g_Qh + ((size_t)bh*SEQ + q0 + r)*HD + ch*8);
    }
    if (tid < 64) cp4(sb + 512 + tid*4, g_tileskip + b*64 + tid);
    f_loadK(sb, bh, 0, tid, 0); f_loadV(sb, bh, 0, tid, 0); f_loadMB(sb, b, 0, tid, 0);
    CP_COMMIT();
    f_loadK(sb, bh, 1, tid, 1); f_loadV(sb, bh, 1, tid, 1); f_loadMB(sb, b, 1, tid, 1);
    CP_COMMIT();

    float o[2][8][4];
#pragma unroll
    for (int mi=0;mi<2;mi++)
#pragma unroll
        for (int j=0;j<8;j++)
#pragma unroll
            for (int x=0;x<4;x++) o[mi][j][x]=0.f;
    float racc[2][4];
#pragma unroll
    for (int mi=0;mi<2;mi++)
#pragma unroll
        for (int x=0;x<4;x++) racc[mi][x]=0.f;
    uint32_t qf[2][4][4];

    CP_WAIT1();
    __syncthreads();
    {
        const uint32_t* Qu = smU + FQ_B/4;
#pragma unroll
        for (int mi=0;mi<2;mi++)
#pragma unroll
            for (int c=0;c<4;c++){
                const uint32_t* qp = Qu + (wid*32 + mi*16 + g)*36 + c*8 + q4;
                qf[mi][c][0]=qp[0]; qf[mi][c][1]=qp[8*36];
                qf[mi][c][2]=qp[4]; qf[mi][c][3]=qp[8*36+4];
            }
    }

    int cb = 0;
    for (int i=0;i<64;i++){
        CP_WAIT1();
        __syncthreads();

        const int skip = ((const int*)dynsm)[128 + i];
        if (!skip){
            // ---- S = Q K^T (K fragments shared across both m-frags) ----
            float s[2][8][4];
#pragma unroll
            for (int mi=0;mi<2;mi++)
#pragma unroll
                for (int j=0;j<8;j++)
#pragma unroll
                    for (int x=0;x<4;x++) s[mi][j][x]=0.f;
            const uint32_t kb = sb + FK_B + cb*9216 + lofs;
#pragma unroll
            for (int c=0;c<4;c++){
                uint32_t kf[8][2];
#pragma unroll
                for (int jp=0;jp<4;jp++)
                    LDSM4(kf[2*jp][0],kf[2*jp][1],kf[2*jp+1][0],kf[2*jp+1][1], kb + jp*2304 + c*32);
#pragma unroll
                for (int mi=0;mi<2;mi++)
#pragma unroll
                    for (int j=0;j<8;j++)
                        HMMA(s[mi][j], qf[mi][c], kf[j][0], kf[j][1]);
            }

            // ---- softmax in f16x2 ----
            const uint32_t* mbU = smU + cb*32;
            uint32_t pp[2][8][2];
#pragma unroll
            for (int mi=0;mi<2;mi++)
#pragma unroll
                for (int j=0;j<8;j++){
                    uint32_t mb2u = mbU[j*4 + q4];
                    pp[mi][j][0] = ex2h2(hadd2(h2pack(s[mi][j][0], s[mi][j][1]), mb2u));
                    pp[mi][j][1] = ex2h2(hadd2(h2pack(s[mi][j][2], s[mi][j][3]), mb2u));
                }

            // ---- O += P V (V fragments shared); rowsum += P·1 ----
            const uint32_t vb = sb + FV_B + cb*9216 + lofsv;
#pragma unroll
            for (int c=0;c<4;c++){
                uint32_t vf[8][2];
#pragma unroll
                for (int jp=0;jp<4;jp++)
                    LDSM4_T(vf[2*jp][0],vf[2*jp][1],vf[2*jp+1][0],vf[2*jp+1][1], vb + c*2304 + jp*32);
#pragma unroll
                for (int mi=0;mi<2;mi++){
                    uint32_t A[4] = {pp[mi][2*c][0], pp[mi][2*c][1], pp[mi][2*c+1][0], pp[mi][2*c+1][1]};
#pragma unroll
                    for (int jn=0;jn<8;jn++)
                        HMMA(o[mi][jn], A, vf[jn][0], vf[jn][1]);
                    HMMA(racc[mi], A, ONESH2, ONESH2);
                }
            }
        }

        if (i < 62){
            const int pb = (cb+2>2)? cb-1 : cb+2;
            f_loadK(sb, bh, i+2, tid, pb);
            f_loadV(sb, bh, i+2, tid, pb);
            f_loadMB(sb, b, i+2, tid, pb);
        }
        CP_COMMIT();
        cb = (cb+1==3)? 0 : cb+1;
    }

    // ---- epilogue ----
#pragma unroll
    for (int mi=0;mi<2;mi++){
        const float inv0 = 1.0f/racc[mi][0], inv1 = 1.0f/racc[mi][2];
        const int row0 = q0 + wid*32 + mi*16 + g;
        __half* d0 = g_ctxh + ((size_t)(b*SEQ + row0  ))*EMB + h*HD;
        __half* d1 = g_ctxh + ((size_t)(b*SEQ + row0+8))*EMB + h*HD;
#pragma unroll
        for (int jn=0;jn<8;jn++){
            *(__half2*)(d0 + jn*8 + 2*q4) = __floats2half2_rn(o[mi][jn][0]*inv0, o[mi][jn][1]*inv0);
            *(__half2*)(d1 + jn*8 + 2*q4) = __floats2half2_rn(o[mi][jn][2]*inv1, o[mi][jn][3]*inv1);
        }
    }
}

// ---------------- launch ----------------
extern "C" void kernel_launch(void* const* d_in, const int* in_sizes, int n_in,
                              void* d_out, int out_size)
{
    const float* query=(const float*)d_in[0];
    const float* key_ =(const float*)d_in[1];
    const float* value=(const float*)d_in[2];
    const float* Wq=(const float*)d_in[3];  const float* bq=(const float*)d_in[4];
    const float* Wk=(const float*)d_in[5];  const float* bk=(const float*)d_in[6];
    const float* Wv=(const float*)d_in[7];  const float* bv=(const float*)d_in[8];
    const float* Wo=(const float*)d_in[9];  const float* bo=(const float*)d_in[10];
    const unsigned char* mask=(const unsigned char*)d_in[11];

    __half *Wh,*Ch;
    cudaGetSymbolAddress((void**)&Wh, g_Wh);
    cudaGetSymbolAddress((void**)&Ch, g_ctxh);

    cudaFuncSetAttribute(flash_h,   cudaFuncAttributeMaxDynamicSharedMemorySize, FSMEM);
    cudaFuncSetAttribute(hgemm_qkv, cudaFuncAttributeMaxDynamicSharedMemorySize, HG_SMEM);
    cudaFuncSetAttribute(hgemm_one, cudaFuncAttributeMaxDynamicSharedMemorySize, HG_SMEM);

    convert_all<<<(NIN+NW+NT+255)/256 + 1,256>>>(query, key_, value, Wq, Wk, Wv, Wo, mask);

    hgemm_qkv<<<dim3(EMB/128, NROWS/128, 3),256,HG_SMEM>>>(bq, bk, bv);

    rope_h<<<(BHTOT*SEQ*16+255)/256,256>>>();

    flash_h<<<dim3(SEQ/128, BHTOT), 128, FSMEM>>>();

    hgemm_one<<<dim3(EMB/128, NROWS/128),256,HG_SMEM>>>(Ch, Wh + 3*(size_t)WE, bo, d_out, 1);
}